// round 6
// baseline (speedup 1.0000x reference)
#include <cuda_runtime.h>
#include <math.h>
#include <stdint.h>

#define DIMQ     1024
#define HEADS    16
#define DHEAD    64
#define SEQ      2048
#define BATCH    2
#define NTOK     (BATCH * SEQ)      // 4096
#define QKV_N    (3 * DIMQ)         // 3072
#define SCALE_A  0.125f             // 1/sqrt(64)
#define LOG2E    1.4426950408889634f

// Scratch (static device globals — allocation-free)
__device__ float g_qkv[(size_t)NTOK * QKV_N];   // [tok][3072]: Q|K|V (tf32-rounded)
__device__ float g_att[(size_t)NTOK * DIMQ];    // attention result (tf32-rounded)
__device__ float g_x[(size_t)NTOK * DIMQ];      // x, tf32-rounded
__device__ float g_wqkv[(size_t)DIMQ * QKV_N];  // W_qkv, tf32-rounded
__device__ float g_wout[(size_t)DIMQ * DIMQ];   // W_out, tf32-rounded

// ---------------------------------------------------------------------------
// helpers
// ---------------------------------------------------------------------------
__device__ __forceinline__ uint32_t f2tf(float x) {
    uint32_t y;
    asm("cvt.rna.tf32.f32 %0, %1;" : "=r"(y) : "f"(x));
    return y;
}
__device__ __forceinline__ float tfbits(float x) {
    return __uint_as_float(f2tf(x));
}
__device__ __forceinline__ void mma_tf32(float* c, const uint32_t* a, const uint32_t* b) {
    asm volatile(
        "mma.sync.aligned.m16n8k8.row.col.f32.tf32.tf32.f32 "
        "{%0,%1,%2,%3},{%4,%5,%6,%7},{%8,%9},{%0,%1,%2,%3};"
        : "+f"(c[0]), "+f"(c[1]), "+f"(c[2]), "+f"(c[3])
        : "r"(a[0]), "r"(a[1]), "r"(a[2]), "r"(a[3]),
          "r"(b[0]), "r"(b[1]));
}
__device__ __forceinline__ uint32_t smem_u32(const void* p) {
    uint32_t a;
    asm("{ .reg .u64 t; cvta.to.shared.u64 t, %1; cvt.u32.u64 %0, t; }"
        : "=r"(a) : "l"(p));
    return a;
}
__device__ __forceinline__ void cp16(uint32_t dst, const void* src) {
    asm volatile("cp.async.ca.shared.global [%0], [%1], 16;"
                 :: "r"(dst), "l"(src) : "memory");
}
#define CP_COMMIT() asm volatile("cp.async.commit_group;" ::: "memory")
#define CP_WAIT_1() asm volatile("cp.async.wait_group 1;" ::: "memory")
#define CP_WAIT_0() asm volatile("cp.async.wait_group 0;" ::: "memory")

// ---------------------------------------------------------------------------
// round-to-tf32 copy (n multiple of 4)
// ---------------------------------------------------------------------------
__global__ void __launch_bounds__(256) round_copy(
    const float* __restrict__ in, float* __restrict__ out, int n)
{
    int i = (blockIdx.x * 256 + threadIdx.x) * 4;
    if (i < n) {
        float4 v = *(const float4*)(in + i);
        v.x = tfbits(v.x); v.y = tfbits(v.y);
        v.z = tfbits(v.z); v.w = tfbits(v.w);
        *(float4*)(out + i) = v;
    }
}

// ---------------------------------------------------------------------------
// tf32 mma.sync GEMM with cp.async double buffering.
// C[M][N] = A[M][K] @ B[K][N] (+bias). Inputs pre-rounded to tf32 — no CVT
// in the hot loop, raw byte copies. 128x128 CTA tile, BK=32, 256 threads
// = 8 warps (4x2), warp tile 32x64.
// As [m][k] stride 36 (frag bank = 4*lq+lr: permutation);
// Bs [k][n] stride 136 (frag bank = 8*lr+lq: permutation).
// round_out!=0 -> output rounded to tf32 (for intermediates).
// ---------------------------------------------------------------------------
#define AS_F   36          // floats per A row
#define BS_F   136         // floats per B row
#define AS_FL  (128 * AS_F)        // floats per A buffer
#define BS_FL  (32 * BS_F)         // floats per B buffer
#define GEMM_SMEM ((2 * AS_FL + 2 * BS_FL) * 4)   // 71680 B

__global__ void __launch_bounds__(256, 2) gemm_cp(
    const float* __restrict__ A, const float* __restrict__ B,
    const float* __restrict__ bias, float* __restrict__ C,
    int M, int N, int K, int round_out)
{
    extern __shared__ float smemf[];
    const uint32_t sbase = smem_u32(smemf);

    const int tid  = threadIdx.x;
    const int lane = tid & 31;
    const int wid  = tid >> 5;
    const int wm   = wid & 3;       // 0..3 -> 32-row slab
    const int wn   = wid >> 2;      // 0..1 -> 64-col slab
    const int lq   = lane >> 2;     // 0..7
    const int lr   = lane & 3;      // 0..3

    const long row0 = (long)blockIdx.y * 128;
    const long col0 = (long)blockIdx.x * 128;

    // copy mappings
    const int a_r  = tid >> 1;           // 0..127
    const int a_c  = (tid & 1) * 16;     // 0 or 16 (floats)
    const int b_r  = tid >> 3;           // 0..31
    const int b_cc = (tid & 7) * 16;     // 0..112 (floats)

    const float* Apt = A + (row0 + a_r) * K + a_c;
    const float* Bpt = B + col0 + b_cc;
    const uint32_t a_dst0 = sbase + (uint32_t)(a_r * AS_F + a_c) * 4;
    const uint32_t b_dst0 = sbase + (uint32_t)(2 * AS_FL) * 4
                          + (uint32_t)(b_r * BS_F + b_cc) * 4;

    float acc[2][8][4];
    #pragma unroll
    for (int mt = 0; mt < 2; mt++)
        #pragma unroll
        for (int nt = 0; nt < 8; nt++)
            #pragma unroll
            for (int i = 0; i < 4; i++) acc[mt][nt][i] = 0.f;

    const int NC = K / 32;

    // prologue: tile 0 -> buffer 0
    #pragma unroll
    for (int j = 0; j < 4; j++) {
        cp16(a_dst0 + j * 16, Apt + j * 4);
        cp16(b_dst0 + j * 16, Bpt + (long)b_r * N + j * 4);
    }
    CP_COMMIT();

    for (int c = 0; c < NC; c++) {
        const int buf = c & 1;
        if (c + 1 < NC) {
            const int nb = buf ^ 1;
            const long kc = (long)(c + 1) * 32;
            const uint32_t ad = a_dst0 + (uint32_t)(nb * AS_FL) * 4;
            const uint32_t bd = b_dst0 + (uint32_t)(nb * BS_FL) * 4;
            #pragma unroll
            for (int j = 0; j < 4; j++) {
                cp16(ad + j * 16, Apt + kc + j * 4);
                cp16(bd + j * 16, Bpt + (kc + b_r) * N + j * 4);
            }
            CP_COMMIT();
            CP_WAIT_1();
        } else {
            CP_WAIT_0();
        }
        __syncthreads();

        const float* Ab = smemf + buf * AS_FL;
        const float* Bb = smemf + 2 * AS_FL + buf * BS_FL;

        #pragma unroll
        for (int ks = 0; ks < 4; ks++) {
            const int kk = ks * 8;
            uint32_t af[2][4];
            #pragma unroll
            for (int mt = 0; mt < 2; mt++) {
                const int m = wm * 32 + mt * 16 + lq;
                af[mt][0] = __float_as_uint(Ab[m * AS_F + kk + lr]);
                af[mt][1] = __float_as_uint(Ab[(m + 8) * AS_F + kk + lr]);
                af[mt][2] = __float_as_uint(Ab[m * AS_F + kk + lr + 4]);
                af[mt][3] = __float_as_uint(Ab[(m + 8) * AS_F + kk + lr + 4]);
            }
            uint32_t bf[8][2];
            #pragma unroll
            for (int nt = 0; nt < 8; nt++) {
                const int n = wn * 64 + nt * 8 + lq;
                bf[nt][0] = __float_as_uint(Bb[(kk + lr) * BS_F + n]);
                bf[nt][1] = __float_as_uint(Bb[(kk + lr + 4) * BS_F + n]);
            }
            #pragma unroll
            for (int mt = 0; mt < 2; mt++)
                #pragma unroll
                for (int nt = 0; nt < 8; nt++)
                    mma_tf32(acc[mt][nt], af[mt], bf[nt]);
        }
        __syncthreads();   // before buf is overwritten two iterations later
    }

    // epilogue
    #pragma unroll
    for (int mt = 0; mt < 2; mt++) {
        long r0 = row0 + wm * 32 + mt * 16 + lq;
        #pragma unroll
        for (int nt = 0; nt < 8; nt++) {
            long c = col0 + wn * 64 + nt * 8 + 2 * lr;
            float bx = 0.f, by = 0.f;
            if (bias) { bx = bias[c]; by = bias[c + 1]; }
            float2 v0, v1;
            v0.x = acc[mt][nt][0] + bx; v0.y = acc[mt][nt][1] + by;
            v1.x = acc[mt][nt][2] + bx; v1.y = acc[mt][nt][3] + by;
            if (round_out) {
                v0.x = tfbits(v0.x); v0.y = tfbits(v0.y);
                v1.x = tfbits(v1.x); v1.y = tfbits(v1.y);
            }
            *(float2*)(C + r0 * N + c)       = v0;
            *(float2*)(C + (r0 + 8) * N + c) = v1;
        }
    }
}

// ---------------------------------------------------------------------------
// tf32 mma.sync flash attention. CTA = 64 q-rows of one (b,h), 4 warps.
// qkv is already tf32-rounded: K/V stored via raw float4 STS (no CVT).
// Output rounded to tf32 (feeds next GEMM).
// ---------------------------------------------------------------------------
#define QK_S 68
#define V_S  72
#define FA_SMEM ((2 * 64 * QK_S + 64 * V_S) * 4)

__global__ void __launch_bounds__(128) flash_attn_tf32(
    const float* __restrict__ qkv, float* __restrict__ out)
{
    extern __shared__ float sm[];
    float (*QPs)[QK_S] = (float(*)[QK_S])(sm);
    float (*Ks)[QK_S]  = (float(*)[QK_S])(sm + 64 * QK_S);
    float (*Vs)[V_S]   = (float(*)[V_S])(sm + 2 * 64 * QK_S);

    const int tid  = threadIdx.x;
    const int lane = tid & 31;
    const int wid  = tid >> 5;
    const int lq   = lane >> 2;
    const int lr   = lane & 3;
    const int wr   = wid * 16;

    const int h  = blockIdx.y;
    const int b  = blockIdx.z;
    const int q0 = blockIdx.x * 64;

    const size_t base = (size_t)b * SEQ * QKV_N;
    const float* qb = qkv + base + h * DHEAD;
    const float* kb = qkv + base + DIMQ + h * DHEAD;
    const float* vb = qkv + base + 2 * DIMQ + h * DHEAD;

    const float qscale = SCALE_A * LOG2E;

    // load Q (scaled, re-rounded) into QPs
    {
        const int r  = tid >> 4;
        const int c4 = (tid & 15) << 2;
        #pragma unroll
        for (int it = 0; it < 8; it++) {
            int row = r + it * 8;
            float4 v = *(const float4*)(qb + (size_t)(q0 + row) * QKV_N + c4);
            QPs[row][c4 + 0] = tfbits(v.x * qscale);
            QPs[row][c4 + 1] = tfbits(v.y * qscale);
            QPs[row][c4 + 2] = tfbits(v.z * qscale);
            QPs[row][c4 + 3] = tfbits(v.w * qscale);
        }
    }
    __syncthreads();

    uint32_t qf[8][4];
    {
        const int m = wr + lq;
        #pragma unroll
        for (int kk = 0; kk < 8; kk++) {
            qf[kk][0] = __float_as_uint(QPs[m][kk * 8 + lr]);
            qf[kk][1] = __float_as_uint(QPs[m + 8][kk * 8 + lr]);
            qf[kk][2] = __float_as_uint(QPs[m][kk * 8 + lr + 4]);
            qf[kk][3] = __float_as_uint(QPs[m + 8][kk * 8 + lr + 4]);
        }
    }
    __syncthreads();   // QPs now reusable as P buffer

    float o[8][4];
    #pragma unroll
    for (int nt = 0; nt < 8; nt++)
        #pragma unroll
        for (int i = 0; i < 4; i++) o[nt][i] = 0.f;
    float mi_lo = -1e30f, mi_hi = -1e30f, li_lo = 0.f, li_hi = 0.f;

    const int ld_r  = tid >> 4;
    const int ld_c4 = (tid & 15) << 2;

    for (int kt = 0; kt < SEQ; kt += 64) {
        // load K,V tile -> smem (already tf32-rounded: raw float4 copies)
        #pragma unroll
        for (int it = 0; it < 8; it++) {
            int row = ld_r + it * 8;
            float4 kv = *(const float4*)(kb + (size_t)(kt + row) * QKV_N + ld_c4);
            *(float4*)&Ks[row][ld_c4] = kv;
            float4 vv = *(const float4*)(vb + (size_t)(kt + row) * QKV_N + ld_c4);
            *(float4*)&Vs[row][ld_c4] = vv;
        }
        __syncthreads();

        float c[8][4];
        #pragma unroll
        for (int nt = 0; nt < 8; nt++)
            #pragma unroll
            for (int i = 0; i < 4; i++) c[nt][i] = 0.f;

        #pragma unroll
        for (int kk = 0; kk < 8; kk++) {
            uint32_t bf[8][2];
            #pragma unroll
            for (int nt = 0; nt < 8; nt++) {
                int n = nt * 8 + lq;
                bf[nt][0] = __float_as_uint(Ks[n][kk * 8 + lr]);
                bf[nt][1] = __float_as_uint(Ks[n][kk * 8 + lr + 4]);
            }
            #pragma unroll
            for (int nt = 0; nt < 8; nt++)
                mma_tf32(c[nt], qf[kk], bf[nt]);
        }

        float mlo = -1e30f, mhi = -1e30f;
        #pragma unroll
        for (int nt = 0; nt < 8; nt++) {
            mlo = fmaxf(mlo, fmaxf(c[nt][0], c[nt][1]));
            mhi = fmaxf(mhi, fmaxf(c[nt][2], c[nt][3]));
        }
        mlo = fmaxf(mlo, __shfl_xor_sync(0xffffffffu, mlo, 1));
        mlo = fmaxf(mlo, __shfl_xor_sync(0xffffffffu, mlo, 2));
        mhi = fmaxf(mhi, __shfl_xor_sync(0xffffffffu, mhi, 1));
        mhi = fmaxf(mhi, __shfl_xor_sync(0xffffffffu, mhi, 2));

        float mn_lo = fmaxf(mi_lo, mlo);
        float mn_hi = fmaxf(mi_hi, mhi);
        float corr_lo = exp2f(mi_lo - mn_lo);
        float corr_hi = exp2f(mi_hi - mn_hi);
        mi_lo = mn_lo; mi_hi = mn_hi;

        float rs_lo = 0.f, rs_hi = 0.f;
        #pragma unroll
        for (int nt = 0; nt < 8; nt++) {
            c[nt][0] = exp2f(c[nt][0] - mn_lo);
            c[nt][1] = exp2f(c[nt][1] - mn_lo);
            c[nt][2] = exp2f(c[nt][2] - mn_hi);
            c[nt][3] = exp2f(c[nt][3] - mn_hi);
            rs_lo += c[nt][0] + c[nt][1];
            rs_hi += c[nt][2] + c[nt][3];
        }
        rs_lo += __shfl_xor_sync(0xffffffffu, rs_lo, 1);
        rs_lo += __shfl_xor_sync(0xffffffffu, rs_lo, 2);
        rs_hi += __shfl_xor_sync(0xffffffffu, rs_hi, 1);
        rs_hi += __shfl_xor_sync(0xffffffffu, rs_hi, 2);

        li_lo = li_lo * corr_lo + rs_lo;
        li_hi = li_hi * corr_hi + rs_hi;

        #pragma unroll
        for (int nt = 0; nt < 8; nt++) {
            o[nt][0] *= corr_lo; o[nt][1] *= corr_lo;
            o[nt][2] *= corr_hi; o[nt][3] *= corr_hi;
            int col = nt * 8 + 2 * lr;
            QPs[wr + lq][col]     = tfbits(c[nt][0]);
            QPs[wr + lq][col + 1] = tfbits(c[nt][1]);
            QPs[wr + lq + 8][col]     = tfbits(c[nt][2]);
            QPs[wr + lq + 8][col + 1] = tfbits(c[nt][3]);
        }
        __syncthreads();

        #pragma unroll
        for (int kk = 0; kk < 8; kk++) {
            uint32_t ap[4];
            const int m = wr + lq;
            ap[0] = __float_as_uint(QPs[m][kk * 8 + lr]);
            ap[1] = __float_as_uint(QPs[m + 8][kk * 8 + lr]);
            ap[2] = __float_as_uint(QPs[m][kk * 8 + lr + 4]);
            ap[3] = __float_as_uint(QPs[m + 8][kk * 8 + lr + 4]);
            #pragma unroll
            for (int nt = 0; nt < 8; nt++) {
                uint32_t bf[2];
                bf[0] = __float_as_uint(Vs[kk * 8 + lr][nt * 8 + lq]);
                bf[1] = __float_as_uint(Vs[kk * 8 + lr + 4][nt * 8 + lq]);
                mma_tf32(o[nt], ap, bf);
            }
        }
        __syncthreads();
    }

    // epilogue: normalize, round to tf32 (feeds GEMM-3 A)
    const float inv_lo = 1.f / li_lo;
    const float inv_hi = 1.f / li_hi;
    float* ob = out + ((size_t)b * SEQ + q0) * DIMQ + h * DHEAD;
    #pragma unroll
    for (int nt = 0; nt < 8; nt++) {
        int col = nt * 8 + 2 * lr;
        int m = wr + lq;
        float2 v0, v1;
        v0.x = tfbits(o[nt][0] * inv_lo); v0.y = tfbits(o[nt][1] * inv_lo);
        v1.x = tfbits(o[nt][2] * inv_hi); v1.y = tfbits(o[nt][3] * inv_hi);
        *(float2*)(ob + (size_t)m * DIMQ + col)       = v0;
        *(float2*)(ob + (size_t)(m + 8) * DIMQ + col) = v1;
    }
}

// ---------------------------------------------------------------------------
// Launch
// ---------------------------------------------------------------------------
extern "C" void kernel_launch(void* const* d_in, const int* in_sizes, int n_in,
                              void* d_out, int out_size)
{
    const float* x    = (const float*)d_in[0];   // [2,2048,1024]
    const float* Wqkv = (const float*)d_in[1];   // [1024,3072]
    const float* Wout = (const float*)d_in[2];   // [1024,1024]
    const float* bout = (const float*)d_in[3];   // [1024]
    float* out = (float*)d_out;                  // [2,2048,1024]

    float *qkv, *att, *xr, *wqkvr, *woutr;
    cudaGetSymbolAddress((void**)&qkv, g_qkv);
    cudaGetSymbolAddress((void**)&att, g_att);
    cudaGetSymbolAddress((void**)&xr, g_x);
    cudaGetSymbolAddress((void**)&wqkvr, g_wqkv);
    cudaGetSymbolAddress((void**)&woutr, g_wout);

    cudaFuncSetAttribute(gemm_cp,
                         cudaFuncAttributeMaxDynamicSharedMemorySize, GEMM_SMEM);
    cudaFuncSetAttribute(flash_attn_tf32,
                         cudaFuncAttributeMaxDynamicSharedMemorySize, FA_SMEM);

    // Stage 0: pre-round inputs to tf32
    {
        int nx = NTOK * DIMQ, nq = DIMQ * QKV_N, no = DIMQ * DIMQ;
        round_copy<<<(nx / 4 + 255) / 256, 256>>>(x, xr, nx);
        round_copy<<<(nq / 4 + 255) / 256, 256>>>(Wqkv, wqkvr, nq);
        round_copy<<<(no / 4 + 255) / 256, 256>>>(Wout, woutr, no);
    }

    // Stage 1: qkv = x @ W_qkv  (4096 x 3072 x 1024), rounded output
    {
        dim3 grid(QKV_N / 128, NTOK / 128);
        gemm_cp<<<grid, 256, GEMM_SMEM>>>(xr, wqkvr, nullptr, qkv,
                                          NTOK, QKV_N, DIMQ, 1);
    }

    // Stage 2: flash attention
    {
        dim3 grid(SEQ / 64, HEADS, BATCH);
        flash_attn_tf32<<<grid, 128, FA_SMEM>>>(qkv, att);
    }

    // Stage 3: out = att @ W_out + b_out  (4096 x 1024 x 1024), fp32 output
    {
        dim3 grid(DIMQ / 128, NTOK / 128);
        gemm_cp<<<grid, 256, GEMM_SMEM>>>(att, woutr, bout, out,
                                          NTOK, DIMQ, DIMQ, 0);
    }
}

// round 7
// speedup vs baseline: 1.0613x; 1.0613x over previous
#include <cuda_runtime.h>
#include <math.h>
#include <stdint.h>

#define DIMQ     1024
#define HEADS    16
#define DHEAD    64
#define SEQ      2048
#define BATCH    2
#define NTOK     (BATCH * SEQ)      // 4096
#define QKV_N    (3 * DIMQ)         // 3072
#define SCALE_A  0.125f             // 1/sqrt(64)
#define LOG2E    1.4426950408889634f

// Scratch (static device globals — allocation-free)
__device__ float g_qkv[(size_t)NTOK * QKV_N];  // [tok][3072]: Q|K|V (tf32-rounded)
__device__ float g_att[(size_t)NTOK * DIMQ];   // attention result (tf32-rounded)

// ---------------------------------------------------------------------------
// helpers
// ---------------------------------------------------------------------------
__device__ __forceinline__ uint32_t f2tf(float x) {
    uint32_t y;
    asm("cvt.rna.tf32.f32 %0, %1;" : "=r"(y) : "f"(x));
    return y;
}
__device__ __forceinline__ float tfbits(float x) {
    return __uint_as_float(f2tf(x));
}
__device__ __forceinline__ void mma_tf32(float* c, const uint32_t* a, const uint32_t* b) {
    asm volatile(
        "mma.sync.aligned.m16n8k8.row.col.f32.tf32.tf32.f32 "
        "{%0,%1,%2,%3},{%4,%5,%6,%7},{%8,%9},{%0,%1,%2,%3};"
        : "+f"(c[0]), "+f"(c[1]), "+f"(c[2]), "+f"(c[3])
        : "r"(a[0]), "r"(a[1]), "r"(a[2]), "r"(a[3]),
          "r"(b[0]), "r"(b[1]));
}

// ---------------------------------------------------------------------------
// tf32 mma.sync GEMM (R4 structure — measured best). C = A @ B (+bias).
// 128x128 CTA tile, BK=16, 256 threads = 8 warps (4x2), warp tile 32x64.
// Double-buffered smem, reg prefetch. As [k][m] transposed, Bs [k][n],
// stride 136 (conflict-free fragment LDS). round_out -> tf32-rounded C.
// ---------------------------------------------------------------------------
#define GS 136

__global__ void __launch_bounds__(256, 2) sgemm_tf32(
    const float* __restrict__ A, const float* __restrict__ B,
    const float* __restrict__ bias, float* __restrict__ C,
    int M, int N, int K, int round_out)
{
    __shared__ float As[2][16][GS];
    __shared__ float Bs[2][16][GS];

    const int tid  = threadIdx.x;
    const int lane = tid & 31;
    const int wid  = tid >> 5;
    const int wm   = wid & 3;
    const int wn   = wid >> 2;
    const int lq   = lane >> 2;
    const int lr   = lane & 3;

    const long row0 = (long)blockIdx.y * 128;
    const long col0 = (long)blockIdx.x * 128;

    const int a_r = tid >> 1;
    const int a_c = (tid & 1) * 4;
    const int b_r = tid >> 5;
    const int b_c = (tid & 31) * 4;

    const float* Ap = A + (row0 + a_r) * K + a_c;
    const float* Bp = B + col0 + b_c;

    float acc[2][8][4];
    #pragma unroll
    for (int mt = 0; mt < 2; mt++)
        #pragma unroll
        for (int nt = 0; nt < 8; nt++)
            #pragma unroll
            for (int i = 0; i < 4; i++) acc[mt][nt][i] = 0.f;

    float4 pa0 = *(const float4*)(Ap);
    float4 pa1 = *(const float4*)(Ap + 8);
    float4 pb0 = *(const float4*)(Bp + (long)b_r * N);
    float4 pb1 = *(const float4*)(Bp + (long)(b_r + 8) * N);

    {
        As[0][a_c + 0][a_r] = tfbits(pa0.x);
        As[0][a_c + 1][a_r] = tfbits(pa0.y);
        As[0][a_c + 2][a_r] = tfbits(pa0.z);
        As[0][a_c + 3][a_r] = tfbits(pa0.w);
        As[0][a_c + 8][a_r]  = tfbits(pa1.x);
        As[0][a_c + 9][a_r]  = tfbits(pa1.y);
        As[0][a_c + 10][a_r] = tfbits(pa1.z);
        As[0][a_c + 11][a_r] = tfbits(pa1.w);
        float4 t0, t1;
        t0.x = tfbits(pb0.x); t0.y = tfbits(pb0.y);
        t0.z = tfbits(pb0.z); t0.w = tfbits(pb0.w);
        t1.x = tfbits(pb1.x); t1.y = tfbits(pb1.y);
        t1.z = tfbits(pb1.z); t1.w = tfbits(pb1.w);
        *(float4*)&Bs[0][b_r][b_c]     = t0;
        *(float4*)&Bs[0][b_r + 8][b_c] = t1;
    }
    __syncthreads();

    int buf = 0;
    for (int k0 = 0; k0 < K; k0 += 16) {
        const bool more = (k0 + 16 < K);
        if (more) {
            pa0 = *(const float4*)(Ap + k0 + 16);
            pa1 = *(const float4*)(Ap + k0 + 24);
            pb0 = *(const float4*)(Bp + (long)(k0 + 16 + b_r) * N);
            pb1 = *(const float4*)(Bp + (long)(k0 + 24 + b_r) * N);
        }

        #pragma unroll
        for (int ks = 0; ks < 2; ks++) {
            const int kk = ks * 8;
            uint32_t af[2][4];
            #pragma unroll
            for (int mt = 0; mt < 2; mt++) {
                int m = wm * 32 + mt * 16 + lq;
                af[mt][0] = __float_as_uint(As[buf][kk + lr][m]);
                af[mt][1] = __float_as_uint(As[buf][kk + lr][m + 8]);
                af[mt][2] = __float_as_uint(As[buf][kk + lr + 4][m]);
                af[mt][3] = __float_as_uint(As[buf][kk + lr + 4][m + 8]);
            }
            uint32_t bf[8][2];
            #pragma unroll
            for (int nt = 0; nt < 8; nt++) {
                int n = wn * 64 + nt * 8 + lq;
                bf[nt][0] = __float_as_uint(Bs[buf][kk + lr][n]);
                bf[nt][1] = __float_as_uint(Bs[buf][kk + lr + 4][n]);
            }
            #pragma unroll
            for (int mt = 0; mt < 2; mt++)
                #pragma unroll
                for (int nt = 0; nt < 8; nt++)
                    mma_tf32(acc[mt][nt], af[mt], bf[nt]);
        }

        if (more) {
            const int nb = buf ^ 1;
            As[nb][a_c + 0][a_r] = tfbits(pa0.x);
            As[nb][a_c + 1][a_r] = tfbits(pa0.y);
            As[nb][a_c + 2][a_r] = tfbits(pa0.z);
            As[nb][a_c + 3][a_r] = tfbits(pa0.w);
            As[nb][a_c + 8][a_r]  = tfbits(pa1.x);
            As[nb][a_c + 9][a_r]  = tfbits(pa1.y);
            As[nb][a_c + 10][a_r] = tfbits(pa1.z);
            As[nb][a_c + 11][a_r] = tfbits(pa1.w);
            float4 t0, t1;
            t0.x = tfbits(pb0.x); t0.y = tfbits(pb0.y);
            t0.z = tfbits(pb0.z); t0.w = tfbits(pb0.w);
            t1.x = tfbits(pb1.x); t1.y = tfbits(pb1.y);
            t1.z = tfbits(pb1.z); t1.w = tfbits(pb1.w);
            *(float4*)&Bs[nb][b_r][b_c]     = t0;
            *(float4*)&Bs[nb][b_r + 8][b_c] = t1;
            __syncthreads();
            buf = nb;
        }
    }

    #pragma unroll
    for (int mt = 0; mt < 2; mt++) {
        long r0 = row0 + wm * 32 + mt * 16 + lq;
        #pragma unroll
        for (int nt = 0; nt < 8; nt++) {
            long c = col0 + wn * 64 + nt * 8 + 2 * lr;
            float bx = 0.f, by = 0.f;
            if (bias) { bx = bias[c]; by = bias[c + 1]; }
            float2 v0, v1;
            v0.x = acc[mt][nt][0] + bx; v0.y = acc[mt][nt][1] + by;
            v1.x = acc[mt][nt][2] + bx; v1.y = acc[mt][nt][3] + by;
            if (round_out) {
                v0.x = tfbits(v0.x); v0.y = tfbits(v0.y);
                v1.x = tfbits(v1.x); v1.y = tfbits(v1.y);
            }
            *(float2*)(C + r0 * N + c)       = v0;
            *(float2*)(C + (r0 + 8) * N + c) = v1;
        }
    }
}

// ---------------------------------------------------------------------------
// tf32 mma.sync flash attention v2. CTA = 128 q-rows of one (b,h), 8 warps
// (256 threads); warp w owns q-rows [w*16, w*16+16). Key tiles of 64.
// K/V gmem loads amortized over 128 q-rows (2x fewer than v1); raw float4
// smem copies (qkv pre-rounded to tf32 by GEMM-1 epilogue).
// smem: QPs (Q, reused as P) [128][68], Ks [64][68], Vs [64][72] = 70.7KB.
// ---------------------------------------------------------------------------
#define QK_S 68
#define V_S  72
#define FA_SMEM ((192 * QK_S + 64 * V_S) * 4)

__global__ void __launch_bounds__(256, 2) flash_attn_tf32(
    const float* __restrict__ qkv, float* __restrict__ out)
{
    extern __shared__ float sm[];
    float (*QPs)[QK_S] = (float(*)[QK_S])(sm);               // [128][68]
    float (*Ks)[QK_S]  = (float(*)[QK_S])(sm + 128 * QK_S);  // [64][68]
    float (*Vs)[V_S]   = (float(*)[V_S])(sm + 192 * QK_S);   // [64][72]

    const int tid  = threadIdx.x;
    const int lane = tid & 31;
    const int wid  = tid >> 5;       // 0..7
    const int lq   = lane >> 2;
    const int lr   = lane & 3;
    const int wr   = wid * 16;       // q-row base within CTA

    const int h  = blockIdx.y;
    const int b  = blockIdx.z;
    const int q0 = blockIdx.x * 128;

    const size_t base = (size_t)b * SEQ * QKV_N;
    const float* qb = qkv + base + h * DHEAD;
    const float* kb = qkv + base + DIMQ + h * DHEAD;
    const float* vb = qkv + base + 2 * DIMQ + h * DHEAD;

    const float qscale = SCALE_A * LOG2E;

    // load Q tile (128 rows x 64): scale + re-round (scaling changes bits)
    {
        const int r  = tid >> 4;           // 0..15
        const int c4 = (tid & 15) << 2;    // 0..60
        #pragma unroll
        for (int it = 0; it < 8; it++) {
            int row = r + it * 16;
            float4 v = *(const float4*)(qb + (size_t)(q0 + row) * QKV_N + c4);
            QPs[row][c4 + 0] = tfbits(v.x * qscale);
            QPs[row][c4 + 1] = tfbits(v.y * qscale);
            QPs[row][c4 + 2] = tfbits(v.z * qscale);
            QPs[row][c4 + 3] = tfbits(v.w * qscale);
        }
    }
    __syncthreads();

    // preload Q fragments (8 k-steps x 4 regs)
    uint32_t qf[8][4];
    {
        const int m = wr + lq;
        #pragma unroll
        for (int kk = 0; kk < 8; kk++) {
            qf[kk][0] = __float_as_uint(QPs[m][kk * 8 + lr]);
            qf[kk][1] = __float_as_uint(QPs[m + 8][kk * 8 + lr]);
            qf[kk][2] = __float_as_uint(QPs[m][kk * 8 + lr + 4]);
            qf[kk][3] = __float_as_uint(QPs[m + 8][kk * 8 + lr + 4]);
        }
    }
    __syncthreads();   // QPs now reusable as P buffer

    float o[8][4];
    #pragma unroll
    for (int nt = 0; nt < 8; nt++)
        #pragma unroll
        for (int i = 0; i < 4; i++) o[nt][i] = 0.f;
    float mi_lo = -1e30f, mi_hi = -1e30f, li_lo = 0.f, li_hi = 0.f;

    const int ld_r  = tid >> 4;          // 0..15
    const int ld_c4 = (tid & 15) << 2;   // 0..60

    for (int kt = 0; kt < SEQ; kt += 64) {
        // load K,V tile (64 rows) -> smem, raw float4 (already tf32)
        #pragma unroll
        for (int it = 0; it < 4; it++) {
            int row = ld_r + it * 16;
            *(float4*)&Ks[row][ld_c4] =
                *(const float4*)(kb + (size_t)(kt + row) * QKV_N + ld_c4);
            *(float4*)&Vs[row][ld_c4] =
                *(const float4*)(vb + (size_t)(kt + row) * QKV_N + ld_c4);
        }
        __syncthreads();

        // S = Q K^T (exp2-domain scaling folded into Q)
        float c[8][4];
        #pragma unroll
        for (int nt = 0; nt < 8; nt++)
            #pragma unroll
            for (int i = 0; i < 4; i++) c[nt][i] = 0.f;

        #pragma unroll
        for (int kk = 0; kk < 8; kk++) {
            uint32_t bf[8][2];
            #pragma unroll
            for (int nt = 0; nt < 8; nt++) {
                int n = nt * 8 + lq;
                bf[nt][0] = __float_as_uint(Ks[n][kk * 8 + lr]);
                bf[nt][1] = __float_as_uint(Ks[n][kk * 8 + lr + 4]);
            }
            #pragma unroll
            for (int nt = 0; nt < 8; nt++)
                mma_tf32(c[nt], qf[kk], bf[nt]);
        }

        // online softmax on fragments
        float mlo = -1e30f, mhi = -1e30f;
        #pragma unroll
        for (int nt = 0; nt < 8; nt++) {
            mlo = fmaxf(mlo, fmaxf(c[nt][0], c[nt][1]));
            mhi = fmaxf(mhi, fmaxf(c[nt][2], c[nt][3]));
        }
        mlo = fmaxf(mlo, __shfl_xor_sync(0xffffffffu, mlo, 1));
        mlo = fmaxf(mlo, __shfl_xor_sync(0xffffffffu, mlo, 2));
        mhi = fmaxf(mhi, __shfl_xor_sync(0xffffffffu, mhi, 1));
        mhi = fmaxf(mhi, __shfl_xor_sync(0xffffffffu, mhi, 2));

        float mn_lo = fmaxf(mi_lo, mlo);
        float mn_hi = fmaxf(mi_hi, mhi);
        float corr_lo = exp2f(mi_lo - mn_lo);
        float corr_hi = exp2f(mi_hi - mn_hi);
        mi_lo = mn_lo; mi_hi = mn_hi;

        float rs_lo = 0.f, rs_hi = 0.f;
        #pragma unroll
        for (int nt = 0; nt < 8; nt++) {
            c[nt][0] = exp2f(c[nt][0] - mn_lo);
            c[nt][1] = exp2f(c[nt][1] - mn_lo);
            c[nt][2] = exp2f(c[nt][2] - mn_hi);
            c[nt][3] = exp2f(c[nt][3] - mn_hi);
            rs_lo += c[nt][0] + c[nt][1];
            rs_hi += c[nt][2] + c[nt][3];
        }
        rs_lo += __shfl_xor_sync(0xffffffffu, rs_lo, 1);
        rs_lo += __shfl_xor_sync(0xffffffffu, rs_lo, 2);
        rs_hi += __shfl_xor_sync(0xffffffffu, rs_hi, 1);
        rs_hi += __shfl_xor_sync(0xffffffffu, rs_hi, 2);

        li_lo = li_lo * corr_lo + rs_lo;
        li_hi = li_hi * corr_hi + rs_hi;

        // rescale O, store P (tf32) into QPs
        #pragma unroll
        for (int nt = 0; nt < 8; nt++) {
            o[nt][0] *= corr_lo; o[nt][1] *= corr_lo;
            o[nt][2] *= corr_hi; o[nt][3] *= corr_hi;
            int col = nt * 8 + 2 * lr;
            QPs[wr + lq][col]     = tfbits(c[nt][0]);
            QPs[wr + lq][col + 1] = tfbits(c[nt][1]);
            QPs[wr + lq + 8][col]     = tfbits(c[nt][2]);
            QPs[wr + lq + 8][col + 1] = tfbits(c[nt][3]);
        }
        __syncthreads();

        // O += P @ V
        #pragma unroll
        for (int kk = 0; kk < 8; kk++) {
            uint32_t ap[4];
            const int m = wr + lq;
            ap[0] = __float_as_uint(QPs[m][kk * 8 + lr]);
            ap[1] = __float_as_uint(QPs[m + 8][kk * 8 + lr]);
            ap[2] = __float_as_uint(QPs[m][kk * 8 + lr + 4]);
            ap[3] = __float_as_uint(QPs[m + 8][kk * 8 + lr + 4]);
            #pragma unroll
            for (int nt = 0; nt < 8; nt++) {
                uint32_t bf[2];
                bf[0] = __float_as_uint(Vs[kk * 8 + lr][nt * 8 + lq]);
                bf[1] = __float_as_uint(Vs[kk * 8 + lr + 4][nt * 8 + lq]);
                mma_tf32(o[nt], ap, bf);
            }
        }
        __syncthreads();   // protect Ks/Vs/QPs for next iteration
    }

    // epilogue: normalize, round to tf32 (feeds GEMM-3)
    const float inv_lo = 1.f / li_lo;
    const float inv_hi = 1.f / li_hi;
    float* ob = out + ((size_t)b * SEQ + q0) * DIMQ + h * DHEAD;
    #pragma unroll
    for (int nt = 0; nt < 8; nt++) {
        int col = nt * 8 + 2 * lr;
        int m = wr + lq;
        float2 v0, v1;
        v0.x = tfbits(o[nt][0] * inv_lo); v0.y = tfbits(o[nt][1] * inv_lo);
        v1.x = tfbits(o[nt][2] * inv_hi); v1.y = tfbits(o[nt][3] * inv_hi);
        *(float2*)(ob + (size_t)m * DIMQ + col)       = v0;
        *(float2*)(ob + (size_t)(m + 8) * DIMQ + col) = v1;
    }
}

// ---------------------------------------------------------------------------
// Launch
// ---------------------------------------------------------------------------
extern "C" void kernel_launch(void* const* d_in, const int* in_sizes, int n_in,
                              void* d_out, int out_size)
{
    const float* x    = (const float*)d_in[0];   // [2,2048,1024]
    const float* Wqkv = (const float*)d_in[1];   // [1024,3072]
    const float* Wout = (const float*)d_in[2];   // [1024,1024]
    const float* bout = (const float*)d_in[3];   // [1024]
    float* out = (float*)d_out;                  // [2,2048,1024]

    float *qkv, *att;
    cudaGetSymbolAddress((void**)&qkv, g_qkv);
    cudaGetSymbolAddress((void**)&att, g_att);

    cudaFuncSetAttribute(flash_attn_tf32,
                         cudaFuncAttributeMaxDynamicSharedMemorySize, FA_SMEM);

    // Stage 1: qkv = x @ W_qkv  (4096 x 3072 x 1024), tf32-rounded output
    {
        dim3 grid(QKV_N / 128, NTOK / 128);
        sgemm_tf32<<<grid, 256>>>(x, Wqkv, nullptr, qkv, NTOK, QKV_N, DIMQ, 1);
    }

    // Stage 2: flash attention (128 q-rows per CTA)
    {
        dim3 grid(SEQ / 128, HEADS, BATCH);
        flash_attn_tf32<<<grid, 256, FA_SMEM>>>(qkv, att);
    }

    // Stage 3: out = att @ W_out + b_out  (4096 x 1024 x 1024)
    {
        dim3 grid(DIMQ / 128, NTOK / 128);
        sgemm_tf32<<<grid, 256>>>(att, Wout, bout, out, NTOK, DIMQ, DIMQ, 0);
    }
}

// round 8
// speedup vs baseline: 1.0951x; 1.0319x over previous
#include <cuda_runtime.h>
#include <math.h>
#include <stdint.h>

#define DIMQ     1024
#define HEADS    16
#define DHEAD    64
#define SEQ      2048
#define BATCH    2
#define NTOK     (BATCH * SEQ)      // 4096
#define QKV_N    (3 * DIMQ)         // 3072
#define SCALE_A  0.125f             // 1/sqrt(64)
#define LOG2E    1.4426950408889634f

// Scratch (static device globals — allocation-free)
__device__ float g_qkv[(size_t)NTOK * QKV_N];  // [tok][3072]: Q|K|V (tf32-rounded)
__device__ float g_att[(size_t)NTOK * DIMQ];   // attention result (tf32-rounded)

// ---------------------------------------------------------------------------
// helpers
// ---------------------------------------------------------------------------
__device__ __forceinline__ uint32_t f2tf(float x) {
    uint32_t y;
    asm("cvt.rna.tf32.f32 %0, %1;" : "=r"(y) : "f"(x));
    return y;
}
__device__ __forceinline__ float tfbits(float x) {
    return __uint_as_float(f2tf(x));
}
__device__ __forceinline__ void mma_tf32(float* c, const uint32_t* a, const uint32_t* b) {
    asm volatile(
        "mma.sync.aligned.m16n8k8.row.col.f32.tf32.tf32.f32 "
        "{%0,%1,%2,%3},{%4,%5,%6,%7},{%8,%9},{%0,%1,%2,%3};"
        : "+f"(c[0]), "+f"(c[1]), "+f"(c[2]), "+f"(c[3])
        : "r"(a[0]), "r"(a[1]), "r"(a[2]), "r"(a[3]),
          "r"(b[0]), "r"(b[1]));
}
__device__ __forceinline__ void ldsm_x4(uint32_t* r, uint32_t addr) {
    asm volatile("ldmatrix.sync.aligned.m8n8.x4.shared.b16 {%0,%1,%2,%3}, [%4];"
                 : "=r"(r[0]), "=r"(r[1]), "=r"(r[2]), "=r"(r[3]) : "r"(addr));
}
__device__ __forceinline__ uint32_t smem_u32(const void* p) {
    uint32_t a;
    asm("{ .reg .u64 t; cvta.to.shared.u64 t, %1; cvt.u32.u64 %0, t; }"
        : "=r"(a) : "l"(p));
    return a;
}

// ---------------------------------------------------------------------------
// tf32 mma.sync GEMM with ldmatrix fragment loads. C = A @ B (+bias).
// 128x128 CTA tile, BK=16, 256 threads = 8 warps (4x2), warp tile 32x64.
// As [m][k] rows of 16 floats padded to 20 (80B, 16B-multiple, conflict-free
// LDSM groups 5r mod 8). Bst [n][k] same stride — B transposed on the fly by
// reading gmem along k (coalesced across n). Double-buffered, reg prefetch.
// round_out -> tf32-rounded C. A tf32 8x4 tile == 8x8 b16 matrix for LDSM.
// ---------------------------------------------------------------------------
#define AST 20   // row stride in floats (80 bytes)

__global__ void __launch_bounds__(256, 2) sgemm_tf32(
    const float* __restrict__ A, const float* __restrict__ B,
    const float* __restrict__ bias, float* __restrict__ C,
    int M, int N, int K, int round_out)
{
    __shared__ float As[2][128 * AST];
    __shared__ float Bst[2][128 * AST];

    const int tid  = threadIdx.x;
    const int lane = tid & 31;
    const int wid  = tid >> 5;
    const int wm   = wid & 3;       // 0..3 -> 32-row slab
    const int wn   = wid >> 2;      // 0..1 -> 64-col slab

    const long row0 = (long)blockIdx.y * 128;
    const long col0 = (long)blockIdx.x * 128;

    // writer mapping: thread owns A row w_m (k-half w_h) and B col n=w_m
    const int w_m = tid & 127;
    const int w_h = tid >> 7;            // 0/1 -> k in [0,8) or [8,16)

    const float* Ap = A + (row0 + w_m) * K + w_h * 8;
    const float* Bp = B + col0 + w_m;    // + k*N per element

    // LDSM per-lane address components
    const uint32_t as_base[2] = { smem_u32(As[0]),  smem_u32(As[1])  };
    const uint32_t bs_base[2] = { smem_u32(Bst[0]), smem_u32(Bst[1]) };
    const int a_row = lane & 15;               // + m0
    const int a_col = (lane >> 4) * 4;         // + kk
    const int b_row = (lane & 7) + ((lane >> 4) << 3);   // + n0
    const int b_col = ((lane >> 3) & 1) * 4;             // + kk

    float acc[2][8][4];
    #pragma unroll
    for (int mt = 0; mt < 2; mt++)
        #pragma unroll
        for (int nt = 0; nt < 8; nt++)
            #pragma unroll
            for (int i = 0; i < 4; i++) acc[mt][nt][i] = 0.f;

    // prefetch tile 0
    float4 pa0 = *(const float4*)(Ap);
    float4 pa1 = *(const float4*)(Ap + 4);
    float pb[8];
    #pragma unroll
    for (int j = 0; j < 8; j++) pb[j] = Bp[(long)(w_h * 8 + j) * N];

    // store tile 0 -> buffer 0
    {
        float4 ta0, ta1, tb0, tb1;
        ta0.x = tfbits(pa0.x); ta0.y = tfbits(pa0.y);
        ta0.z = tfbits(pa0.z); ta0.w = tfbits(pa0.w);
        ta1.x = tfbits(pa1.x); ta1.y = tfbits(pa1.y);
        ta1.z = tfbits(pa1.z); ta1.w = tfbits(pa1.w);
        tb0.x = tfbits(pb[0]); tb0.y = tfbits(pb[1]);
        tb0.z = tfbits(pb[2]); tb0.w = tfbits(pb[3]);
        tb1.x = tfbits(pb[4]); tb1.y = tfbits(pb[5]);
        tb1.z = tfbits(pb[6]); tb1.w = tfbits(pb[7]);
        *(float4*)&As[0][w_m * AST + w_h * 8]      = ta0;
        *(float4*)&As[0][w_m * AST + w_h * 8 + 4]  = ta1;
        *(float4*)&Bst[0][w_m * AST + w_h * 8]     = tb0;
        *(float4*)&Bst[0][w_m * AST + w_h * 8 + 4] = tb1;
    }
    __syncthreads();

    int buf = 0;
    for (int k0 = 0; k0 < K; k0 += 16) {
        const bool more = (k0 + 16 < K);
        if (more) {
            const long kc = k0 + 16;
            pa0 = *(const float4*)(Ap + kc);
            pa1 = *(const float4*)(Ap + kc + 4);
            #pragma unroll
            for (int j = 0; j < 8; j++) pb[j] = Bp[(kc + w_h * 8 + j) * N];
        }

        // compute on buf
        #pragma unroll
        for (int ks = 0; ks < 2; ks++) {
            const int kk = ks * 8;
            uint32_t af[2][4];
            #pragma unroll
            for (int mt = 0; mt < 2; mt++) {
                const int m0 = wm * 32 + mt * 16;
                ldsm_x4(af[mt], as_base[buf]
                        + (uint32_t)((m0 + a_row) * AST + kk + a_col) * 4);
            }
            uint32_t bf[8][2];
            #pragma unroll
            for (int bg = 0; bg < 4; bg++) {
                uint32_t t[4];
                const int n0 = wn * 64 + bg * 16;
                ldsm_x4(t, bs_base[buf]
                        + (uint32_t)((n0 + b_row) * AST + kk + b_col) * 4);
                bf[bg * 2][0]     = t[0];
                bf[bg * 2][1]     = t[1];
                bf[bg * 2 + 1][0] = t[2];
                bf[bg * 2 + 1][1] = t[3];
            }
            #pragma unroll
            for (int mt = 0; mt < 2; mt++)
                #pragma unroll
                for (int nt = 0; nt < 8; nt++)
                    mma_tf32(acc[mt][nt], af[mt], bf[nt]);
        }

        if (more) {
            const int nb = buf ^ 1;
            float4 ta0, ta1, tb0, tb1;
            ta0.x = tfbits(pa0.x); ta0.y = tfbits(pa0.y);
            ta0.z = tfbits(pa0.z); ta0.w = tfbits(pa0.w);
            ta1.x = tfbits(pa1.x); ta1.y = tfbits(pa1.y);
            ta1.z = tfbits(pa1.z); ta1.w = tfbits(pa1.w);
            tb0.x = tfbits(pb[0]); tb0.y = tfbits(pb[1]);
            tb0.z = tfbits(pb[2]); tb0.w = tfbits(pb[3]);
            tb1.x = tfbits(pb[4]); tb1.y = tfbits(pb[5]);
            tb1.z = tfbits(pb[6]); tb1.w = tfbits(pb[7]);
            *(float4*)&As[nb][w_m * AST + w_h * 8]      = ta0;
            *(float4*)&As[nb][w_m * AST + w_h * 8 + 4]  = ta1;
            *(float4*)&Bst[nb][w_m * AST + w_h * 8]     = tb0;
            *(float4*)&Bst[nb][w_m * AST + w_h * 8 + 4] = tb1;
            __syncthreads();
            buf = nb;
        }
    }

    // epilogue (acc layout: rows lq/lq+8, cols 2lr/2lr+1 per n-tile)
    const int lq = lane >> 2;
    const int lr = lane & 3;
    #pragma unroll
    for (int mt = 0; mt < 2; mt++) {
        long r0 = row0 + wm * 32 + mt * 16 + lq;
        #pragma unroll
        for (int nt = 0; nt < 8; nt++) {
            long c = col0 + wn * 64 + nt * 8 + 2 * lr;
            float bx = 0.f, by = 0.f;
            if (bias) { bx = bias[c]; by = bias[c + 1]; }
            float2 v0, v1;
            v0.x = acc[mt][nt][0] + bx; v0.y = acc[mt][nt][1] + by;
            v1.x = acc[mt][nt][2] + bx; v1.y = acc[mt][nt][3] + by;
            if (round_out) {
                v0.x = tfbits(v0.x); v0.y = tfbits(v0.y);
                v1.x = tfbits(v1.x); v1.y = tfbits(v1.y);
            }
            *(float2*)(C + r0 * N + c)       = v0;
            *(float2*)(C + (r0 + 8) * N + c) = v1;
        }
    }
}

// ---------------------------------------------------------------------------
// tf32 mma.sync flash attention (R7 version, unchanged). CTA = 128 q-rows,
// 8 warps. qkv pre-rounded to tf32 -> raw float4 K/V copies.
// ---------------------------------------------------------------------------
#define QK_S 68
#define V_S  72
#define FA_SMEM ((192 * QK_S + 64 * V_S) * 4)

__global__ void __launch_bounds__(256, 2) flash_attn_tf32(
    const float* __restrict__ qkv, float* __restrict__ out)
{
    extern __shared__ float sm[];
    float (*QPs)[QK_S] = (float(*)[QK_S])(sm);
    float (*Ks)[QK_S]  = (float(*)[QK_S])(sm + 128 * QK_S);
    float (*Vs)[V_S]   = (float(*)[V_S])(sm + 192 * QK_S);

    const int tid  = threadIdx.x;
    const int lane = tid & 31;
    const int wid  = tid >> 5;
    const int lq   = lane >> 2;
    const int lr   = lane & 3;
    const int wr   = wid * 16;

    const int h  = blockIdx.y;
    const int b  = blockIdx.z;
    const int q0 = blockIdx.x * 128;

    const size_t base = (size_t)b * SEQ * QKV_N;
    const float* qb = qkv + base + h * DHEAD;
    const float* kb = qkv + base + DIMQ + h * DHEAD;
    const float* vb = qkv + base + 2 * DIMQ + h * DHEAD;

    const float qscale = SCALE_A * LOG2E;

    {
        const int r  = tid >> 4;
        const int c4 = (tid & 15) << 2;
        #pragma unroll
        for (int it = 0; it < 8; it++) {
            int row = r + it * 16;
            float4 v = *(const float4*)(qb + (size_t)(q0 + row) * QKV_N + c4);
            QPs[row][c4 + 0] = tfbits(v.x * qscale);
            QPs[row][c4 + 1] = tfbits(v.y * qscale);
            QPs[row][c4 + 2] = tfbits(v.z * qscale);
            QPs[row][c4 + 3] = tfbits(v.w * qscale);
        }
    }
    __syncthreads();

    uint32_t qf[8][4];
    {
        const int m = wr + lq;
        #pragma unroll
        for (int kk = 0; kk < 8; kk++) {
            qf[kk][0] = __float_as_uint(QPs[m][kk * 8 + lr]);
            qf[kk][1] = __float_as_uint(QPs[m + 8][kk * 8 + lr]);
            qf[kk][2] = __float_as_uint(QPs[m][kk * 8 + lr + 4]);
            qf[kk][3] = __float_as_uint(QPs[m + 8][kk * 8 + lr + 4]);
        }
    }
    __syncthreads();

    float o[8][4];
    #pragma unroll
    for (int nt = 0; nt < 8; nt++)
        #pragma unroll
        for (int i = 0; i < 4; i++) o[nt][i] = 0.f;
    float mi_lo = -1e30f, mi_hi = -1e30f, li_lo = 0.f, li_hi = 0.f;

    const int ld_r  = tid >> 4;
    const int ld_c4 = (tid & 15) << 2;

    for (int kt = 0; kt < SEQ; kt += 64) {
        #pragma unroll
        for (int it = 0; it < 4; it++) {
            int row = ld_r + it * 16;
            *(float4*)&Ks[row][ld_c4] =
                *(const float4*)(kb + (size_t)(kt + row) * QKV_N + ld_c4);
            *(float4*)&Vs[row][ld_c4] =
                *(const float4*)(vb + (size_t)(kt + row) * QKV_N + ld_c4);
        }
        __syncthreads();

        float c[8][4];
        #pragma unroll
        for (int nt = 0; nt < 8; nt++)
            #pragma unroll
            for (int i = 0; i < 4; i++) c[nt][i] = 0.f;

        #pragma unroll
        for (int kk = 0; kk < 8; kk++) {
            uint32_t bf[8][2];
            #pragma unroll
            for (int nt = 0; nt < 8; nt++) {
                int n = nt * 8 + lq;
                bf[nt][0] = __float_as_uint(Ks[n][kk * 8 + lr]);
                bf[nt][1] = __float_as_uint(Ks[n][kk * 8 + lr + 4]);
            }
            #pragma unroll
            for (int nt = 0; nt < 8; nt++)
                mma_tf32(c[nt], qf[kk], bf[nt]);
        }

        float mlo = -1e30f, mhi = -1e30f;
        #pragma unroll
        for (int nt = 0; nt < 8; nt++) {
            mlo = fmaxf(mlo, fmaxf(c[nt][0], c[nt][1]));
            mhi = fmaxf(mhi, fmaxf(c[nt][2], c[nt][3]));
        }
        mlo = fmaxf(mlo, __shfl_xor_sync(0xffffffffu, mlo, 1));
        mlo = fmaxf(mlo, __shfl_xor_sync(0xffffffffu, mlo, 2));
        mhi = fmaxf(mhi, __shfl_xor_sync(0xffffffffu, mhi, 1));
        mhi = fmaxf(mhi, __shfl_xor_sync(0xffffffffu, mhi, 2));

        float mn_lo = fmaxf(mi_lo, mlo);
        float mn_hi = fmaxf(mi_hi, mhi);
        float corr_lo = exp2f(mi_lo - mn_lo);
        float corr_hi = exp2f(mi_hi - mn_hi);
        mi_lo = mn_lo; mi_hi = mn_hi;

        float rs_lo = 0.f, rs_hi = 0.f;
        #pragma unroll
        for (int nt = 0; nt < 8; nt++) {
            c[nt][0] = exp2f(c[nt][0] - mn_lo);
            c[nt][1] = exp2f(c[nt][1] - mn_lo);
            c[nt][2] = exp2f(c[nt][2] - mn_hi);
            c[nt][3] = exp2f(c[nt][3] - mn_hi);
            rs_lo += c[nt][0] + c[nt][1];
            rs_hi += c[nt][2] + c[nt][3];
        }
        rs_lo += __shfl_xor_sync(0xffffffffu, rs_lo, 1);
        rs_lo += __shfl_xor_sync(0xffffffffu, rs_lo, 2);
        rs_hi += __shfl_xor_sync(0xffffffffu, rs_hi, 1);
        rs_hi += __shfl_xor_sync(0xffffffffu, rs_hi, 2);

        li_lo = li_lo * corr_lo + rs_lo;
        li_hi = li_hi * corr_hi + rs_hi;

        #pragma unroll
        for (int nt = 0; nt < 8; nt++) {
            o[nt][0] *= corr_lo; o[nt][1] *= corr_lo;
            o[nt][2] *= corr_hi; o[nt][3] *= corr_hi;
            int col = nt * 8 + 2 * lr;
            QPs[wr + lq][col]     = tfbits(c[nt][0]);
            QPs[wr + lq][col + 1] = tfbits(c[nt][1]);
            QPs[wr + lq + 8][col]     = tfbits(c[nt][2]);
            QPs[wr + lq + 8][col + 1] = tfbits(c[nt][3]);
        }
        __syncthreads();

        #pragma unroll
        for (int kk = 0; kk < 8; kk++) {
            uint32_t ap[4];
            const int m = wr + lq;
            ap[0] = __float_as_uint(QPs[m][kk * 8 + lr]);
            ap[1] = __float_as_uint(QPs[m + 8][kk * 8 + lr]);
            ap[2] = __float_as_uint(QPs[m][kk * 8 + lr + 4]);
            ap[3] = __float_as_uint(QPs[m + 8][kk * 8 + lr + 4]);
            #pragma unroll
            for (int nt = 0; nt < 8; nt++) {
                uint32_t bf[2];
                bf[0] = __float_as_uint(Vs[kk * 8 + lr][nt * 8 + lq]);
                bf[1] = __float_as_uint(Vs[kk * 8 + lr + 4][nt * 8 + lq]);
                mma_tf32(o[nt], ap, bf);
            }
        }
        __syncthreads();
    }

    const float inv_lo = 1.f / li_lo;
    const float inv_hi = 1.f / li_hi;
    float* ob = out + ((size_t)b * SEQ + q0) * DIMQ + h * DHEAD;
    #pragma unroll
    for (int nt = 0; nt < 8; nt++) {
        int col = nt * 8 + 2 * lr;
        int m = wr + lq;
        float2 v0, v1;
        v0.x = tfbits(o[nt][0] * inv_lo); v0.y = tfbits(o[nt][1] * inv_lo);
        v1.x = tfbits(o[nt][2] * inv_hi); v1.y = tfbits(o[nt][3] * inv_hi);
        *(float2*)(ob + (size_t)m * DIMQ + col)       = v0;
        *(float2*)(ob + (size_t)(m + 8) * DIMQ + col) = v1;
    }
}

// ---------------------------------------------------------------------------
// Launch
// ---------------------------------------------------------------------------
extern "C" void kernel_launch(void* const* d_in, const int* in_sizes, int n_in,
                              void* d_out, int out_size)
{
    const float* x    = (const float*)d_in[0];   // [2,2048,1024]
    const float* Wqkv = (const float*)d_in[1];   // [1024,3072]
    const float* Wout = (const float*)d_in[2];   // [1024,1024]
    const float* bout = (const float*)d_in[3];   // [1024]
    float* out = (float*)d_out;                  // [2,2048,1024]

    float *qkv, *att;
    cudaGetSymbolAddress((void**)&qkv, g_qkv);
    cudaGetSymbolAddress((void**)&att, g_att);

    cudaFuncSetAttribute(flash_attn_tf32,
                         cudaFuncAttributeMaxDynamicSharedMemorySize, FA_SMEM);

    // Stage 1: qkv = x @ W_qkv  (4096 x 3072 x 1024), tf32-rounded output
    {
        dim3 grid(QKV_N / 128, NTOK / 128);
        sgemm_tf32<<<grid, 256>>>(x, Wqkv, nullptr, qkv, NTOK, QKV_N, DIMQ, 1);
    }

    // Stage 2: flash attention (128 q-rows per CTA)
    {
        dim3 grid(SEQ / 128, HEADS, BATCH);
        flash_attn_tf32<<<grid, 256, FA_SMEM>>>(qkv, att);
    }

    // Stage 3: out = att @ W_out + b_out  (4096 x 1024 x 1024)
    {
        dim3 grid(DIMQ / 128, NTOK / 128);
        sgemm_tf32<<<grid, 256>>>(att, Wout, bout, out, NTOK, DIMQ, DIMQ, 0);
    }
}

// round 9
// speedup vs baseline: 1.7184x; 1.5691x over previous
#include <cuda_runtime.h>
#include <cuda_fp16.h>
#include <math.h>
#include <stdint.h>

#define DIMQ     1024
#define HEADS    16
#define DHEAD    64
#define SEQ      2048
#define BATCH    2
#define NTOK     (BATCH * SEQ)      // 4096
#define QKV_N    (3 * DIMQ)         // 3072
#define SCALE_A  0.125f             // 1/sqrt(64)
#define LOG2E    1.4426950408889634f

// Scratch (static device globals — allocation-free)
__device__ __half g_qkv[(size_t)NTOK * QKV_N];   // Q|K|V fp16
__device__ __half g_att[(size_t)NTOK * DIMQ];    // attention result fp16
__device__ __half g_xh[(size_t)NTOK * DIMQ];     // x fp16 [m][k]
__device__ __half g_wqkvT[(size_t)QKV_N * DIMQ]; // W_qkv^T fp16 [n][k]
__device__ __half g_woutT[(size_t)DIMQ * DIMQ];  // W_out^T fp16 [n][k]

// ---------------------------------------------------------------------------
// helpers
// ---------------------------------------------------------------------------
__device__ __forceinline__ uint32_t smem_u32(const void* p) {
    uint32_t a;
    asm("{ .reg .u64 t; cvta.to.shared.u64 t, %1; cvt.u32.u64 %0, t; }"
        : "=r"(a) : "l"(p));
    return a;
}
__device__ __forceinline__ void mma_f16(float* c, const uint32_t* a, const uint32_t* b) {
    asm volatile(
        "mma.sync.aligned.m16n8k16.row.col.f32.f16.f16.f32 "
        "{%0,%1,%2,%3},{%4,%5,%6,%7},{%8,%9},{%0,%1,%2,%3};"
        : "+f"(c[0]), "+f"(c[1]), "+f"(c[2]), "+f"(c[3])
        : "r"(a[0]), "r"(a[1]), "r"(a[2]), "r"(a[3]),
          "r"(b[0]), "r"(b[1]));
}
__device__ __forceinline__ void ldsm_x4(uint32_t* r, uint32_t addr) {
    asm volatile("ldmatrix.sync.aligned.m8n8.x4.shared.b16 {%0,%1,%2,%3}, [%4];"
                 : "=r"(r[0]), "=r"(r[1]), "=r"(r[2]), "=r"(r[3]) : "r"(addr));
}
__device__ __forceinline__ void ldsm_x4_t(uint32_t* r, uint32_t addr) {
    asm volatile("ldmatrix.sync.aligned.m8n8.x4.trans.shared.b16 {%0,%1,%2,%3}, [%4];"
                 : "=r"(r[0]), "=r"(r[1]), "=r"(r[2]), "=r"(r[3]) : "r"(addr));
}

// ---------------------------------------------------------------------------
// f32 -> f16 convert (n multiple of 8)
// ---------------------------------------------------------------------------
__global__ void __launch_bounds__(256) f32_to_f16(
    const float* __restrict__ in, __half* __restrict__ out, int n)
{
    int i = (blockIdx.x * 256 + threadIdx.x) * 8;
    if (i < n) {
        float4 a = *(const float4*)(in + i);
        float4 b = *(const float4*)(in + i + 4);
        __half2 h[4];
        h[0] = __floats2half2_rn(a.x, a.y);
        h[1] = __floats2half2_rn(a.z, a.w);
        h[2] = __floats2half2_rn(b.x, b.y);
        h[3] = __floats2half2_rn(b.z, b.w);
        *(uint4*)(out + i) = *(uint4*)h;
    }
}

// f32 [R][C] -> f16 transposed [C][R]
__global__ void __launch_bounds__(256) f32_to_f16_T(
    const float* __restrict__ in, __half* __restrict__ out, int R, int C)
{
    __shared__ float t[32][33];
    int bx = blockIdx.x * 32, by = blockIdx.y * 32;
    int x = threadIdx.x, y = threadIdx.y;   // 32 x 8
    #pragma unroll
    for (int i = 0; i < 32; i += 8)
        t[y + i][x] = in[(size_t)(by + y + i) * C + bx + x];
    __syncthreads();
    #pragma unroll
    for (int i = 0; i < 32; i += 8)
        out[(size_t)(bx + y + i) * R + by + x] = __float2half(t[x][y + i]);
}

// ---------------------------------------------------------------------------
// fp16 mma.sync GEMM: C[M][N] = A[M][K] @ BT[N][K]^T (+bias).
// 128x128 CTA tile, BK=32, 256 threads = 8 warps (4x2), warp tile 32x64.
// As/Bs [row][k] halves, stride 40 (80B: 16B-aligned rows, conflict-free
// padded-stride LDSM — same word geometry as validated R8 AST=20 floats).
// Double-buffered, reg prefetch. out_half -> fp16 C, else f32 (+bias).
// ---------------------------------------------------------------------------
#define HST 40   // halves per smem row

__global__ void __launch_bounds__(256, 2) gemm_f16(
    const __half* __restrict__ A, const __half* __restrict__ BT,
    const float* __restrict__ bias, void* __restrict__ Cout,
    int M, int N, int K, int out_half)
{
    __shared__ __half As[2][128 * HST];
    __shared__ __half Bs[2][128 * HST];

    const int tid  = threadIdx.x;
    const int lane = tid & 31;
    const int wid  = tid >> 5;
    const int wm   = wid & 3;       // 32-row slab
    const int wn   = wid >> 2;      // 64-col slab

    const long row0 = (long)blockIdx.y * 128;
    const long col0 = (long)blockIdx.x * 128;

    const int w_m = tid & 127;
    const int w_h = tid >> 7;       // chunk-pair 0/1 -> k halves 0..15 / 16..31

    const __half* Ap = A  + (size_t)(row0 + w_m) * K + w_h * 16;
    const __half* Bp = BT + (size_t)(col0 + w_m) * K + w_h * 16;

    const uint32_t as_b[2] = { smem_u32(As[0]), smem_u32(As[1]) };
    const uint32_t bs_b[2] = { smem_u32(Bs[0]), smem_u32(Bs[1]) };
    const uint32_t a_off = (uint32_t)((lane & 15) * HST + (lane >> 4) * 8) * 2;
    const uint32_t b_off = (uint32_t)(((lane & 7) + ((lane >> 4) << 3)) * HST
                                      + ((lane >> 3) & 1) * 8) * 2;
    const uint32_t sts_off = (uint32_t)(w_m * HST + w_h * 16);

    float acc[2][8][4];
    #pragma unroll
    for (int mt = 0; mt < 2; mt++)
        #pragma unroll
        for (int nt = 0; nt < 8; nt++)
            #pragma unroll
            for (int i = 0; i < 4; i++) acc[mt][nt][i] = 0.f;

    uint4 pa0 = *(const uint4*)(Ap);
    uint4 pa1 = *(const uint4*)(Ap + 8);
    uint4 pb0 = *(const uint4*)(Bp);
    uint4 pb1 = *(const uint4*)(Bp + 8);

    *(uint4*)&As[0][sts_off]     = pa0;
    *(uint4*)&As[0][sts_off + 8] = pa1;
    *(uint4*)&Bs[0][sts_off]     = pb0;
    *(uint4*)&Bs[0][sts_off + 8] = pb1;
    __syncthreads();

    int buf = 0;
    for (int k0 = 0; k0 < K; k0 += 32) {
        const bool more = (k0 + 32 < K);
        if (more) {
            pa0 = *(const uint4*)(Ap + k0 + 32);
            pa1 = *(const uint4*)(Ap + k0 + 40);
            pb0 = *(const uint4*)(Bp + k0 + 32);
            pb1 = *(const uint4*)(Bp + k0 + 40);
        }

        #pragma unroll
        for (int ks = 0; ks < 2; ks++) {
            uint32_t af[2][4];
            #pragma unroll
            for (int mt = 0; mt < 2; mt++)
                ldsm_x4(af[mt], as_b[buf]
                        + (uint32_t)((wm * 32 + mt * 16) * HST + ks * 16) * 2
                        + a_off);
            uint32_t bf[8][2];
            #pragma unroll
            for (int bg = 0; bg < 4; bg++) {
                uint32_t t[4];
                ldsm_x4(t, bs_b[buf]
                        + (uint32_t)((wn * 64 + bg * 16) * HST + ks * 16) * 2
                        + b_off);
                bf[bg * 2][0]     = t[0];
                bf[bg * 2][1]     = t[1];
                bf[bg * 2 + 1][0] = t[2];
                bf[bg * 2 + 1][1] = t[3];
            }
            #pragma unroll
            for (int mt = 0; mt < 2; mt++)
                #pragma unroll
                for (int nt = 0; nt < 8; nt++)
                    mma_f16(acc[mt][nt], af[mt], bf[nt]);
        }

        if (more) {
            const int nb = buf ^ 1;
            *(uint4*)&As[nb][sts_off]     = pa0;
            *(uint4*)&As[nb][sts_off + 8] = pa1;
            *(uint4*)&Bs[nb][sts_off]     = pb0;
            *(uint4*)&Bs[nb][sts_off + 8] = pb1;
            __syncthreads();
            buf = nb;
        }
    }

    // epilogue: acc rows lq/lq+8, cols 2lr/2lr+1 per n-tile
    const int lq = lane >> 2;
    const int lr = lane & 3;
    if (out_half) {
        __half* Ch = (__half*)Cout;
        #pragma unroll
        for (int mt = 0; mt < 2; mt++) {
            long r0 = row0 + wm * 32 + mt * 16 + lq;
            #pragma unroll
            for (int nt = 0; nt < 8; nt++) {
                long c = col0 + wn * 64 + nt * 8 + 2 * lr;
                *(__half2*)(Ch + r0 * N + c) =
                    __floats2half2_rn(acc[mt][nt][0], acc[mt][nt][1]);
                *(__half2*)(Ch + (r0 + 8) * N + c) =
                    __floats2half2_rn(acc[mt][nt][2], acc[mt][nt][3]);
            }
        }
    } else {
        float* Cf = (float*)Cout;
        #pragma unroll
        for (int mt = 0; mt < 2; mt++) {
            long r0 = row0 + wm * 32 + mt * 16 + lq;
            #pragma unroll
            for (int nt = 0; nt < 8; nt++) {
                long c = col0 + wn * 64 + nt * 8 + 2 * lr;
                float bx = bias ? bias[c] : 0.f;
                float by = bias ? bias[c + 1] : 0.f;
                float2 v0, v1;
                v0.x = acc[mt][nt][0] + bx; v0.y = acc[mt][nt][1] + by;
                v1.x = acc[mt][nt][2] + bx; v1.y = acc[mt][nt][3] + by;
                *(float2*)(Cf + r0 * N + c)       = v0;
                *(float2*)(Cf + (r0 + 8) * N + c) = v1;
            }
        }
    }
}

// ---------------------------------------------------------------------------
// fp16 mma.sync flash attention. CTA = 128 q-rows of one (b,h), 8 warps.
// All smem tiles: 64-half rows (128B, bank-aligned) with XOR chunk swizzle
// (chunk ^= row&7): conflict-free LDSM and balanced STS.
// K b-frags via ldmatrix; V b-frags via ldmatrix.trans (HW transpose);
// P a-frags via ldmatrix. Q frags preloaded. Softmax in exp2 domain.
// ---------------------------------------------------------------------------
__global__ void __launch_bounds__(256, 2) flash_attn_f16(
    const __half* __restrict__ qkv, __half* __restrict__ out)
{
    __shared__ __half QP[128 * 64];   // Q, then reused as P (warp-private rows)
    __shared__ __half Ks[64 * 64];
    __shared__ __half Vs[64 * 64];

    const int tid  = threadIdx.x;
    const int lane = tid & 31;
    const int wid  = tid >> 5;
    const int lq   = lane >> 2;
    const int lr   = lane & 3;
    const int wr   = wid * 16;       // q-row base of this warp

    const int h  = blockIdx.y;
    const int b  = blockIdx.z;
    const int q0 = blockIdx.x * 128;

    const size_t base = (size_t)b * SEQ * QKV_N;
    const __half* qb = qkv + base + h * DHEAD;
    const __half* kb = qkv + base + DIMQ + h * DHEAD;
    const __half* vb = qkv + base + 2 * DIMQ + h * DHEAD;

    const uint32_t qp_b = smem_u32(QP);
    const uint32_t ks_b = smem_u32(Ks);
    const uint32_t vs_b = smem_u32(Vs);

    const float qscale = SCALE_A * LOG2E;

    // load Q tile (128 x 64 halves), scale in f32, swizzled store
    {
        const int row = tid & 127;
        const int cb  = (tid >> 7) * 4;
        const __half* qrow = qb + (size_t)(q0 + row) * QKV_N;
        #pragma unroll
        for (int j = 0; j < 4; j++) {
            const int c = cb + j;
            uint4 u = *(const uint4*)(qrow + c * 8);
            __half2* hp = (__half2*)&u;
            #pragma unroll
            for (int e = 0; e < 4; e++) {
                float2 f = __half22float2(hp[e]);
                hp[e] = __floats2half2_rn(f.x * qscale, f.y * qscale);
            }
            const int pc = c ^ (row & 7);
            *(uint4*)&QP[row * 64 + pc * 8] = u;
        }
    }
    __syncthreads();

    // preload Q fragments: 4 k16-steps
    uint32_t qf[4][4];
    {
        const int arow = wr + (lane & 15);
        const int x = lane & 7;
        #pragma unroll
        for (int ks = 0; ks < 4; ks++) {
            const int pc = (2 * ks + (lane >> 4)) ^ x;
            ldsm_x4(qf[ks], qp_b + (uint32_t)(arow * 64 + pc * 8) * 2);
        }
    }
    __syncthreads();   // QP reusable as P

    float o[8][4];
    #pragma unroll
    for (int nt = 0; nt < 8; nt++)
        #pragma unroll
        for (int i = 0; i < 4; i++) o[nt][i] = 0.f;
    float mi_lo = -1e30f, mi_hi = -1e30f, li_lo = 0.f, li_hi = 0.f;

    for (int kt = 0; kt < SEQ; kt += 64) {
        // load K,V tile: warp = 4 rows x 8 chunks (coalesced), swizzled store
        #pragma unroll
        for (int it = 0; it < 2; it++) {
            const int row = (tid >> 3) + 32 * it;
            const int c   = tid & 7;
            const int pc  = c ^ (row & 7);
            *(uint4*)&Ks[row * 64 + pc * 8] =
                *(const uint4*)(kb + (size_t)(kt + row) * QKV_N + c * 8);
            *(uint4*)&Vs[row * 64 + pc * 8] =
                *(const uint4*)(vb + (size_t)(kt + row) * QKV_N + c * 8);
        }
        __syncthreads();

        // S = Q K^T
        float c[8][4];
        #pragma unroll
        for (int nt = 0; nt < 8; nt++)
            #pragma unroll
            for (int i = 0; i < 4; i++) c[nt][i] = 0.f;

        #pragma unroll
        for (int ks = 0; ks < 4; ks++) {
            uint32_t bf[8][2];
            #pragma unroll
            for (int bg = 0; bg < 4; bg++) {
                uint32_t t[4];
                const int row = bg * 16 + (lane & 7) + ((lane >> 4) << 3);
                const int pc  = (2 * ks + ((lane >> 3) & 1)) ^ (lane & 7);
                ldsm_x4(t, ks_b + (uint32_t)(row * 64 + pc * 8) * 2);
                bf[bg * 2][0]     = t[0];
                bf[bg * 2][1]     = t[1];
                bf[bg * 2 + 1][0] = t[2];
                bf[bg * 2 + 1][1] = t[3];
            }
            #pragma unroll
            for (int nt = 0; nt < 8; nt++)
                mma_f16(c[nt], qf[ks], bf[nt]);
        }

        // online softmax (exp2 domain)
        float mlo = -1e30f, mhi = -1e30f;
        #pragma unroll
        for (int nt = 0; nt < 8; nt++) {
            mlo = fmaxf(mlo, fmaxf(c[nt][0], c[nt][1]));
            mhi = fmaxf(mhi, fmaxf(c[nt][2], c[nt][3]));
        }
        mlo = fmaxf(mlo, __shfl_xor_sync(0xffffffffu, mlo, 1));
        mlo = fmaxf(mlo, __shfl_xor_sync(0xffffffffu, mlo, 2));
        mhi = fmaxf(mhi, __shfl_xor_sync(0xffffffffu, mhi, 1));
        mhi = fmaxf(mhi, __shfl_xor_sync(0xffffffffu, mhi, 2));

        const float mn_lo = fmaxf(mi_lo, mlo);
        const float mn_hi = fmaxf(mi_hi, mhi);
        const float corr_lo = exp2f(mi_lo - mn_lo);
        const float corr_hi = exp2f(mi_hi - mn_hi);
        mi_lo = mn_lo; mi_hi = mn_hi;

        float rs_lo = 0.f, rs_hi = 0.f;
        #pragma unroll
        for (int nt = 0; nt < 8; nt++) {
            c[nt][0] = exp2f(c[nt][0] - mn_lo);
            c[nt][1] = exp2f(c[nt][1] - mn_lo);
            c[nt][2] = exp2f(c[nt][2] - mn_hi);
            c[nt][3] = exp2f(c[nt][3] - mn_hi);
            rs_lo += c[nt][0] + c[nt][1];
            rs_hi += c[nt][2] + c[nt][3];
        }
        rs_lo += __shfl_xor_sync(0xffffffffu, rs_lo, 1);
        rs_lo += __shfl_xor_sync(0xffffffffu, rs_lo, 2);
        rs_hi += __shfl_xor_sync(0xffffffffu, rs_hi, 1);
        rs_hi += __shfl_xor_sync(0xffffffffu, rs_hi, 2);

        li_lo = li_lo * corr_lo + rs_lo;
        li_hi = li_hi * corr_hi + rs_hi;

        // rescale O, store P fp16 (warp-private rows -> no barrier needed)
        #pragma unroll
        for (int nt = 0; nt < 8; nt++) {
            o[nt][0] *= corr_lo; o[nt][1] *= corr_lo;
            o[nt][2] *= corr_hi; o[nt][3] *= corr_hi;
            const int pc = nt ^ lq;   // (wr+lq)&7 == lq; same for +8
            *(__half2*)&QP[(wr + lq) * 64 + pc * 8 + 2 * lr] =
                __floats2half2_rn(c[nt][0], c[nt][1]);
            *(__half2*)&QP[(wr + lq + 8) * 64 + pc * 8 + 2 * lr] =
                __floats2half2_rn(c[nt][2], c[nt][3]);
        }

        // O += P @ V  (V b-frags via ldmatrix.trans on natural [key][d])
        #pragma unroll
        for (int ks = 0; ks < 4; ks++) {
            uint32_t ap[4];
            {
                const int arow = wr + (lane & 15);
                const int pc = (2 * ks + (lane >> 4)) ^ (lane & 7);
                ldsm_x4(ap, qp_b + (uint32_t)(arow * 64 + pc * 8) * 2);
            }
            uint32_t bf[8][2];
            #pragma unroll
            for (int dt = 0; dt < 4; dt++) {
                uint32_t t[4];
                const int row = ks * 16 + (lane & 7) + ((lane >> 4) << 3);
                const int pc  = (2 * dt + ((lane >> 3) & 1)) ^ (lane & 7);
                ldsm_x4_t(t, vs_b + (uint32_t)(row * 64 + pc * 8) * 2);
                bf[dt * 2][0]     = t[0];
                bf[dt * 2][1]     = t[2];
                bf[dt * 2 + 1][0] = t[1];
                bf[dt * 2 + 1][1] = t[3];
            }
            #pragma unroll
            for (int nt = 0; nt < 8; nt++)
                mma_f16(o[nt], ap, bf[nt]);
        }
        __syncthreads();   // protect Ks/Vs before next tile load
    }

    // epilogue: normalize, fp16 out
    const float inv_lo = 1.f / li_lo;
    const float inv_hi = 1.f / li_hi;
    __half* ob = out + ((size_t)b * SEQ + q0) * DIMQ + h * DHEAD;
    #pragma unroll
    for (int nt = 0; nt < 8; nt++) {
        const int col = nt * 8 + 2 * lr;
        const int m = wr + lq;
        *(__half2*)(ob + (size_t)m * DIMQ + col) =
            __floats2half2_rn(o[nt][0] * inv_lo, o[nt][1] * inv_lo);
        *(__half2*)(ob + (size_t)(m + 8) * DIMQ + col) =
            __floats2half2_rn(o[nt][2] * inv_hi, o[nt][3] * inv_hi);
    }
}

// ---------------------------------------------------------------------------
// Launch
// ---------------------------------------------------------------------------
extern "C" void kernel_launch(void* const* d_in, const int* in_sizes, int n_in,
                              void* d_out, int out_size)
{
    const float* x    = (const float*)d_in[0];   // [2,2048,1024]
    const float* Wqkv = (const float*)d_in[1];   // [1024,3072]
    const float* Wout = (const float*)d_in[2];   // [1024,1024]
    const float* bout = (const float*)d_in[3];   // [1024]
    float* out = (float*)d_out;                  // [2,2048,1024] f32

    __half *qkv, *att, *xh, *wqkvT, *woutT;
    cudaGetSymbolAddress((void**)&qkv, g_qkv);
    cudaGetSymbolAddress((void**)&att, g_att);
    cudaGetSymbolAddress((void**)&xh, g_xh);
    cudaGetSymbolAddress((void**)&wqkvT, g_wqkvT);
    cudaGetSymbolAddress((void**)&woutT, g_woutT);

    // Stage 0: convert x to fp16; convert+transpose weights to [n][k] fp16
    {
        int nx = NTOK * DIMQ;
        f32_to_f16<<<nx / 8 / 256, 256>>>(x, xh, nx);
        f32_to_f16_T<<<dim3(QKV_N / 32, DIMQ / 32), dim3(32, 8)>>>(
            Wqkv, wqkvT, DIMQ, QKV_N);
        f32_to_f16_T<<<dim3(DIMQ / 32, DIMQ / 32), dim3(32, 8)>>>(
            Wout, woutT, DIMQ, DIMQ);
    }

    // Stage 1: qkv = x @ W_qkv  (4096 x 3072 x 1024), fp16 out
    {
        dim3 grid(QKV_N / 128, NTOK / 128);
        gemm_f16<<<grid, 256>>>(xh, wqkvT, nullptr, qkv, NTOK, QKV_N, DIMQ, 1);
    }

    // Stage 2: flash attention (128 q-rows per CTA), fp16 out
    {
        dim3 grid(SEQ / 128, HEADS, BATCH);
        flash_attn_f16<<<grid, 256>>>(qkv, att);
    }

    // Stage 3: out = att @ W_out + b_out  (4096 x 1024 x 1024), f32 out
    {
        dim3 grid(DIMQ / 128, NTOK / 128);
        gemm_f16<<<grid, 256>>>(att, woutT, bout, out, NTOK, DIMQ, DIMQ, 0);
    }
}

// round 11
// speedup vs baseline: 1.7793x; 1.0354x over previous
#include <cuda_runtime.h>
#include <cuda_fp16.h>
#include <math.h>
#include <stdint.h>

#define DIMQ     1024
#define HEADS    16
#define DHEAD    64
#define SEQ      2048
#define BATCH    2
#define NTOK     (BATCH * SEQ)      // 4096
#define QKV_N    (3 * DIMQ)         // 3072
#define SCALE_A  0.125f             // 1/sqrt(64)
#define LOG2E    1.4426950408889634f

// Scratch (static device globals — allocation-free)
__device__ __half g_qkv[(size_t)NTOK * QKV_N];   // Q|K|V fp16
__device__ __half g_att[(size_t)NTOK * DIMQ];    // attention result fp16
__device__ __half g_xh[(size_t)NTOK * DIMQ];     // x fp16 [m][k]
__device__ __half g_wqkvT[(size_t)QKV_N * DIMQ]; // W_qkv^T fp16 [n][k]
__device__ __half g_woutT[(size_t)DIMQ * DIMQ];  // W_out^T fp16 [n][k]

// ---------------------------------------------------------------------------
// helpers
// ---------------------------------------------------------------------------
__device__ __forceinline__ uint32_t smem_u32(const void* p) {
    uint32_t a;
    asm("{ .reg .u64 t; cvta.to.shared.u64 t, %1; cvt.u32.u64 %0, t; }"
        : "=r"(a) : "l"(p));
    return a;
}
__device__ __forceinline__ void mma_f16(float* c, const uint32_t* a, const uint32_t* b) {
    asm volatile(
        "mma.sync.aligned.m16n8k16.row.col.f32.f16.f16.f32 "
        "{%0,%1,%2,%3},{%4,%5,%6,%7},{%8,%9},{%0,%1,%2,%3};"
        : "+f"(c[0]), "+f"(c[1]), "+f"(c[2]), "+f"(c[3])
        : "r"(a[0]), "r"(a[1]), "r"(a[2]), "r"(a[3]),
          "r"(b[0]), "r"(b[1]));
}
__device__ __forceinline__ void ldsm_x4(uint32_t* r, uint32_t addr) {
    asm volatile("ldmatrix.sync.aligned.m8n8.x4.shared.b16 {%0,%1,%2,%3}, [%4];"
                 : "=r"(r[0]), "=r"(r[1]), "=r"(r[2]), "=r"(r[3]) : "r"(addr));
}
__device__ __forceinline__ void ldsm_x4_t(uint32_t* r, uint32_t addr) {
    asm volatile("ldmatrix.sync.aligned.m8n8.x4.trans.shared.b16 {%0,%1,%2,%3}, [%4];"
                 : "=r"(r[0]), "=r"(r[1]), "=r"(r[2]), "=r"(r[3]) : "r"(addr));
}

// ---------------------------------------------------------------------------
// f32 -> f16 convert (n multiple of 8)
// ---------------------------------------------------------------------------
__global__ void __launch_bounds__(256) f32_to_f16(
    const float* __restrict__ in, __half* __restrict__ out, int n)
{
    int i = (blockIdx.x * 256 + threadIdx.x) * 8;
    if (i < n) {
        float4 a = *(const float4*)(in + i);
        float4 b = *(const float4*)(in + i + 4);
        __half2 h[4];
        h[0] = __floats2half2_rn(a.x, a.y);
        h[1] = __floats2half2_rn(a.z, a.w);
        h[2] = __floats2half2_rn(b.x, b.y);
        h[3] = __floats2half2_rn(b.z, b.w);
        *(uint4*)(out + i) = *(uint4*)h;
    }
}

// f32 [R][C] -> f16 transposed [C][R]
__global__ void __launch_bounds__(256) f32_to_f16_T(
    const float* __restrict__ in, __half* __restrict__ out, int R, int C)
{
    __shared__ float t[32][33];
    int bx = blockIdx.x * 32, by = blockIdx.y * 32;
    int x = threadIdx.x, y = threadIdx.y;   // 32 x 8
    #pragma unroll
    for (int i = 0; i < 32; i += 8)
        t[y + i][x] = in[(size_t)(by + y + i) * C + bx + x];
    __syncthreads();
    #pragma unroll
    for (int i = 0; i < 32; i += 8)
        out[(size_t)(bx + y + i) * R + by + x] = __float2half(t[x][y + i]);
}

// ---------------------------------------------------------------------------
// fp16 mma.sync GEMM v2 (copy-stride FIXED): C[M][N] = A[M][K] @ BT[N][K]^T.
// 128x128 CTA tile, BK=32, 128 threads = 4 warps (2x2), warp tile 64x64
// (LDSM wavefronts/MMA = 1.0; A and B each re-read only 2x per CTA).
// Each thread copies one full 32-half row chunk as 4 x uint4 (stride 8).
// smem rows HST=40 halves (80B, conflict-free LDSM). Double-buffered.
// out_half -> fp16 C else f32 (+bias).
// ---------------------------------------------------------------------------
#define HST 40   // halves per smem row

__global__ void __launch_bounds__(128, 2) gemm_f16(
    const __half* __restrict__ A, const __half* __restrict__ BT,
    const float* __restrict__ bias, void* __restrict__ Cout,
    int M, int N, int K, int out_half)
{
    __shared__ __half As[2][128 * HST];
    __shared__ __half Bs[2][128 * HST];

    const int tid  = threadIdx.x;
    const int lane = tid & 31;
    const int wid  = tid >> 5;       // 0..3
    const int wm   = wid & 1;        // 64-row slab
    const int wn   = wid >> 1;       // 64-col slab

    const long row0 = (long)blockIdx.y * 128;
    const long col0 = (long)blockIdx.x * 128;

    // copy mapping: thread t owns full 32-half k-chunk of A row t and B row t
    const __half* Ap = A  + (size_t)(row0 + tid) * K;
    const __half* Bp = BT + (size_t)(col0 + tid) * K;
    const uint32_t sts_off = (uint32_t)(tid * HST);

    const uint32_t as_b[2] = { smem_u32(As[0]), smem_u32(As[1]) };
    const uint32_t bs_b[2] = { smem_u32(Bs[0]), smem_u32(Bs[1]) };
    const uint32_t a_off = (uint32_t)((lane & 15) * HST + (lane >> 4) * 8) * 2;
    const uint32_t b_off = (uint32_t)(((lane & 7) + ((lane >> 4) << 3)) * HST
                                      + ((lane >> 3) & 1) * 8) * 2;

    float acc[4][8][4];
    #pragma unroll
    for (int mt = 0; mt < 4; mt++)
        #pragma unroll
        for (int nt = 0; nt < 8; nt++)
            #pragma unroll
            for (int i = 0; i < 4; i++) acc[mt][nt][i] = 0.f;

    uint4 pa[4], pb[4];
    #pragma unroll
    for (int j = 0; j < 4; j++) {
        pa[j] = *(const uint4*)(Ap + j * 8);
        pb[j] = *(const uint4*)(Bp + j * 8);
    }
    #pragma unroll
    for (int j = 0; j < 4; j++) {
        *(uint4*)&As[0][sts_off + j * 8] = pa[j];
        *(uint4*)&Bs[0][sts_off + j * 8] = pb[j];
    }
    __syncthreads();

    int buf = 0;
    for (int k0 = 0; k0 < K; k0 += 32) {
        const bool more = (k0 + 32 < K);
        if (more) {
            #pragma unroll
            for (int j = 0; j < 4; j++) {
                pa[j] = *(const uint4*)(Ap + k0 + 32 + j * 8);
                pb[j] = *(const uint4*)(Bp + k0 + 32 + j * 8);
            }
        }

        #pragma unroll
        for (int ks = 0; ks < 2; ks++) {
            uint32_t af[4][4];
            #pragma unroll
            for (int mt = 0; mt < 4; mt++)
                ldsm_x4(af[mt], as_b[buf]
                        + (uint32_t)((wm * 64 + mt * 16) * HST + ks * 16) * 2
                        + a_off);
            uint32_t bf[8][2];
            #pragma unroll
            for (int bg = 0; bg < 4; bg++) {
                uint32_t t[4];
                ldsm_x4(t, bs_b[buf]
                        + (uint32_t)((wn * 64 + bg * 16) * HST + ks * 16) * 2
                        + b_off);
                bf[bg * 2][0]     = t[0];
                bf[bg * 2][1]     = t[1];
                bf[bg * 2 + 1][0] = t[2];
                bf[bg * 2 + 1][1] = t[3];
            }
            #pragma unroll
            for (int mt = 0; mt < 4; mt++)
                #pragma unroll
                for (int nt = 0; nt < 8; nt++)
                    mma_f16(acc[mt][nt], af[mt], bf[nt]);
        }

        if (more) {
            const int nb = buf ^ 1;
            #pragma unroll
            for (int j = 0; j < 4; j++) {
                *(uint4*)&As[nb][sts_off + j * 8] = pa[j];
                *(uint4*)&Bs[nb][sts_off + j * 8] = pb[j];
            }
            __syncthreads();
            buf = nb;
        }
    }

    // epilogue: acc rows lq/lq+8, cols 2lr/2lr+1 per n-tile
    const int lq = lane >> 2;
    const int lr = lane & 3;
    if (out_half) {
        __half* Ch = (__half*)Cout;
        #pragma unroll
        for (int mt = 0; mt < 4; mt++) {
            long r0 = row0 + wm * 64 + mt * 16 + lq;
            #pragma unroll
            for (int nt = 0; nt < 8; nt++) {
                long c = col0 + wn * 64 + nt * 8 + 2 * lr;
                *(__half2*)(Ch + r0 * N + c) =
                    __floats2half2_rn(acc[mt][nt][0], acc[mt][nt][1]);
                *(__half2*)(Ch + (r0 + 8) * N + c) =
                    __floats2half2_rn(acc[mt][nt][2], acc[mt][nt][3]);
            }
        }
    } else {
        float* Cf = (float*)Cout;
        #pragma unroll
        for (int mt = 0; mt < 4; mt++) {
            long r0 = row0 + wm * 64 + mt * 16 + lq;
            #pragma unroll
            for (int nt = 0; nt < 8; nt++) {
                long c = col0 + wn * 64 + nt * 8 + 2 * lr;
                float bx = bias ? bias[c] : 0.f;
                float by = bias ? bias[c + 1] : 0.f;
                float2 v0, v1;
                v0.x = acc[mt][nt][0] + bx; v0.y = acc[mt][nt][1] + by;
                v1.x = acc[mt][nt][2] + bx; v1.y = acc[mt][nt][3] + by;
                *(float2*)(Cf + r0 * N + c)       = v0;
                *(float2*)(Cf + (r0 + 8) * N + c) = v1;
            }
        }
    }
}

// ---------------------------------------------------------------------------
// fp16 mma.sync flash attention (R9 version, unchanged). CTA = 128 q-rows,
// 8 warps. XOR-swizzled 128B smem rows; LDSM K/P; ldmatrix.trans V.
// ---------------------------------------------------------------------------
__global__ void __launch_bounds__(256, 2) flash_attn_f16(
    const __half* __restrict__ qkv, __half* __restrict__ out)
{
    __shared__ __half QP[128 * 64];
    __shared__ __half Ks[64 * 64];
    __shared__ __half Vs[64 * 64];

    const int tid  = threadIdx.x;
    const int lane = tid & 31;
    const int wid  = tid >> 5;
    const int lq   = lane >> 2;
    const int lr   = lane & 3;
    const int wr   = wid * 16;

    const int h  = blockIdx.y;
    const int b  = blockIdx.z;
    const int q0 = blockIdx.x * 128;

    const size_t base = (size_t)b * SEQ * QKV_N;
    const __half* qb = qkv + base + h * DHEAD;
    const __half* kb = qkv + base + DIMQ + h * DHEAD;
    const __half* vb = qkv + base + 2 * DIMQ + h * DHEAD;

    const uint32_t qp_b = smem_u32(QP);
    const uint32_t ks_b = smem_u32(Ks);
    const uint32_t vs_b = smem_u32(Vs);

    const float qscale = SCALE_A * LOG2E;

    {
        const int row = tid & 127;
        const int cb  = (tid >> 7) * 4;
        const __half* qrow = qb + (size_t)(q0 + row) * QKV_N;
        #pragma unroll
        for (int j = 0; j < 4; j++) {
            const int c = cb + j;
            uint4 u = *(const uint4*)(qrow + c * 8);
            __half2* hp = (__half2*)&u;
            #pragma unroll
            for (int e = 0; e < 4; e++) {
                float2 f = __half22float2(hp[e]);
                hp[e] = __floats2half2_rn(f.x * qscale, f.y * qscale);
            }
            const int pc = c ^ (row & 7);
            *(uint4*)&QP[row * 64 + pc * 8] = u;
        }
    }
    __syncthreads();

    uint32_t qf[4][4];
    {
        const int arow = wr + (lane & 15);
        const int x = lane & 7;
        #pragma unroll
        for (int ks = 0; ks < 4; ks++) {
            const int pc = (2 * ks + (lane >> 4)) ^ x;
            ldsm_x4(qf[ks], qp_b + (uint32_t)(arow * 64 + pc * 8) * 2);
        }
    }
    __syncthreads();

    float o[8][4];
    #pragma unroll
    for (int nt = 0; nt < 8; nt++)
        #pragma unroll
        for (int i = 0; i < 4; i++) o[nt][i] = 0.f;
    float mi_lo = -1e30f, mi_hi = -1e30f, li_lo = 0.f, li_hi = 0.f;

    for (int kt = 0; kt < SEQ; kt += 64) {
        #pragma unroll
        for (int it = 0; it < 2; it++) {
            const int row = (tid >> 3) + 32 * it;
            const int c   = tid & 7;
            const int pc  = c ^ (row & 7);
            *(uint4*)&Ks[row * 64 + pc * 8] =
                *(const uint4*)(kb + (size_t)(kt + row) * QKV_N + c * 8);
            *(uint4*)&Vs[row * 64 + pc * 8] =
                *(const uint4*)(vb + (size_t)(kt + row) * QKV_N + c * 8);
        }
        __syncthreads();

        float c[8][4];
        #pragma unroll
        for (int nt = 0; nt < 8; nt++)
            #pragma unroll
            for (int i = 0; i < 4; i++) c[nt][i] = 0.f;

        #pragma unroll
        for (int ks = 0; ks < 4; ks++) {
            uint32_t bf[8][2];
            #pragma unroll
            for (int bg = 0; bg < 4; bg++) {
                uint32_t t[4];
                const int row = bg * 16 + (lane & 7) + ((lane >> 4) << 3);
                const int pc  = (2 * ks + ((lane >> 3) & 1)) ^ (lane & 7);
                ldsm_x4(t, ks_b + (uint32_t)(row * 64 + pc * 8) * 2);
                bf[bg * 2][0]     = t[0];
                bf[bg * 2][1]     = t[1];
                bf[bg * 2 + 1][0] = t[2];
                bf[bg * 2 + 1][1] = t[3];
            }
            #pragma unroll
            for (int nt = 0; nt < 8; nt++)
                mma_f16(c[nt], qf[ks], bf[nt]);
        }

        float mlo = -1e30f, mhi = -1e30f;
        #pragma unroll
        for (int nt = 0; nt < 8; nt++) {
            mlo = fmaxf(mlo, fmaxf(c[nt][0], c[nt][1]));
            mhi = fmaxf(mhi, fmaxf(c[nt][2], c[nt][3]));
        }
        mlo = fmaxf(mlo, __shfl_xor_sync(0xffffffffu, mlo, 1));
        mlo = fmaxf(mlo, __shfl_xor_sync(0xffffffffu, mlo, 2));
        mhi = fmaxf(mhi, __shfl_xor_sync(0xffffffffu, mhi, 1));
        mhi = fmaxf(mhi, __shfl_xor_sync(0xffffffffu, mhi, 2));

        const float mn_lo = fmaxf(mi_lo, mlo);
        const float mn_hi = fmaxf(mi_hi, mhi);
        const float corr_lo = exp2f(mi_lo - mn_lo);
        const float corr_hi = exp2f(mi_hi - mn_hi);
        mi_lo = mn_lo; mi_hi = mn_hi;

        float rs_lo = 0.f, rs_hi = 0.f;
        #pragma unroll
        for (int nt = 0; nt < 8; nt++) {
            c[nt][0] = exp2f(c[nt][0] - mn_lo);
            c[nt][1] = exp2f(c[nt][1] - mn_lo);
            c[nt][2] = exp2f(c[nt][2] - mn_hi);
            c[nt][3] = exp2f(c[nt][3] - mn_hi);
            rs_lo += c[nt][0] + c[nt][1];
            rs_hi += c[nt][2] + c[nt][3];
        }
        rs_lo += __shfl_xor_sync(0xffffffffu, rs_lo, 1);
        rs_lo += __shfl_xor_sync(0xffffffffu, rs_lo, 2);
        rs_hi += __shfl_xor_sync(0xffffffffu, rs_hi, 1);
        rs_hi += __shfl_xor_sync(0xffffffffu, rs_hi, 2);

        li_lo = li_lo * corr_lo + rs_lo;
        li_hi = li_hi * corr_hi + rs_hi;

        #pragma unroll
        for (int nt = 0; nt < 8; nt++) {
            o[nt][0] *= corr_lo; o[nt][1] *= corr_lo;
            o[nt][2] *= corr_hi; o[nt][3] *= corr_hi;
            const int pc = nt ^ lq;
            *(__half2*)&QP[(wr + lq) * 64 + pc * 8 + 2 * lr] =
                __floats2half2_rn(c[nt][0], c[nt][1]);
            *(__half2*)&QP[(wr + lq + 8) * 64 + pc * 8 + 2 * lr] =
                __floats2half2_rn(c[nt][2], c[nt][3]);
        }

        #pragma unroll
        for (int ks = 0; ks < 4; ks++) {
            uint32_t ap[4];
            {
                const int arow = wr + (lane & 15);
                const int pc = (2 * ks + (lane >> 4)) ^ (lane & 7);
                ldsm_x4(ap, qp_b + (uint32_t)(arow * 64 + pc * 8) * 2);
            }
            uint32_t bf[8][2];
            #pragma unroll
            for (int dt = 0; dt < 4; dt++) {
                uint32_t t[4];
                const int row = ks * 16 + (lane & 7) + ((lane >> 4) << 3);
                const int pc  = (2 * dt + ((lane >> 3) & 1)) ^ (lane & 7);
                ldsm_x4_t(t, vs_b + (uint32_t)(row * 64 + pc * 8) * 2);
                bf[dt * 2][0]     = t[0];
                bf[dt * 2][1]     = t[2];
                bf[dt * 2 + 1][0] = t[1];
                bf[dt * 2 + 1][1] = t[3];
            }
            #pragma unroll
            for (int nt = 0; nt < 8; nt++)
                mma_f16(o[nt], ap, bf[nt]);
        }
        __syncthreads();
    }

    const float inv_lo = 1.f / li_lo;
    const float inv_hi = 1.f / li_hi;
    __half* ob = out + ((size_t)b * SEQ + q0) * DIMQ + h * DHEAD;
    #pragma unroll
    for (int nt = 0; nt < 8; nt++) {
        const int col = nt * 8 + 2 * lr;
        const int m = wr + lq;
        *(__half2*)(ob + (size_t)m * DIMQ + col) =
            __floats2half2_rn(o[nt][0] * inv_lo, o[nt][1] * inv_lo);
        *(__half2*)(ob + (size_t)(m + 8) * DIMQ + col) =
            __floats2half2_rn(o[nt][2] * inv_hi, o[nt][3] * inv_hi);
    }
}

// ---------------------------------------------------------------------------
// Launch
// ---------------------------------------------------------------------------
extern "C" void kernel_launch(void* const* d_in, const int* in_sizes, int n_in,
                              void* d_out, int out_size)
{
    const float* x    = (const float*)d_in[0];   // [2,2048,1024]
    const float* Wqkv = (const float*)d_in[1];   // [1024,3072]
    const float* Wout = (const float*)d_in[2];   // [1024,1024]
    const float* bout = (const float*)d_in[3];   // [1024]
    float* out = (float*)d_out;                  // [2,2048,1024] f32

    __half *qkv, *att, *xh, *wqkvT, *woutT;
    cudaGetSymbolAddress((void**)&qkv, g_qkv);
    cudaGetSymbolAddress((void**)&att, g_att);
    cudaGetSymbolAddress((void**)&xh, g_xh);
    cudaGetSymbolAddress((void**)&wqkvT, g_wqkvT);
    cudaGetSymbolAddress((void**)&woutT, g_woutT);

    // Stage 0: convert x to fp16; convert+transpose weights to [n][k] fp16
    {
        int nx = NTOK * DIMQ;
        f32_to_f16<<<nx / 8 / 256, 256>>>(x, xh, nx);
        f32_to_f16_T<<<dim3(QKV_N / 32, DIMQ / 32), dim3(32, 8)>>>(
            Wqkv, wqkvT, DIMQ, QKV_N);
        f32_to_f16_T<<<dim3(DIMQ / 32, DIMQ / 32), dim3(32, 8)>>>(
            Wout, woutT, DIMQ, DIMQ);
    }

    // Stage 1: qkv = x @ W_qkv  (4096 x 3072 x 1024), fp16 out
    {
        dim3 grid(QKV_N / 128, NTOK / 128);
        gemm_f16<<<grid, 128>>>(xh, wqkvT, nullptr, qkv, NTOK, QKV_N, DIMQ, 1);
    }

    // Stage 2: flash attention (128 q-rows per CTA), fp16 out
    {
        dim3 grid(SEQ / 128, HEADS, BATCH);
        flash_attn_f16<<<grid, 256>>>(qkv, att);
    }

    // Stage 3: out = att @ W_out + b_out  (4096 x 1024 x 1024), f32 out
    {
        dim3 grid(DIMQ / 128, NTOK / 128);
        gemm_f16<<<grid, 128>>>(att, woutT, bout, out, NTOK, DIMQ, DIMQ, 0);
    }
}

// round 12
// speedup vs baseline: 1.8886x; 1.0614x over previous
#include <cuda_runtime.h>
#include <cuda_fp16.h>
#include <math.h>
#include <stdint.h>

#define DIMQ     1024
#define HEADS    16
#define DHEAD    64
#define SEQ      2048
#define BATCH    2
#define NTOK     (BATCH * SEQ)      // 4096
#define QKV_N    (3 * DIMQ)         // 3072
#define SCALE_A  0.125f             // 1/sqrt(64)
#define LOG2E    1.4426950408889634f

// Scratch (static device globals — allocation-free)
__device__ __half g_qkv[(size_t)NTOK * QKV_N];   // Q|K|V fp16
__device__ __half g_att[(size_t)NTOK * DIMQ];    // attention result fp16
__device__ __half g_xh[(size_t)NTOK * DIMQ];     // x fp16 [m][k]
__device__ __half g_wqkvT[(size_t)QKV_N * DIMQ]; // W_qkv^T fp16 [n][k]
__device__ __half g_woutT[(size_t)DIMQ * DIMQ];  // W_out^T fp16 [n][k]

// ---------------------------------------------------------------------------
// helpers
// ---------------------------------------------------------------------------
__device__ __forceinline__ uint32_t smem_u32(const void* p) {
    uint32_t a;
    asm("{ .reg .u64 t; cvta.to.shared.u64 t, %1; cvt.u32.u64 %0, t; }"
        : "=r"(a) : "l"(p));
    return a;
}
__device__ __forceinline__ void mma_f16(float* c, const uint32_t* a, const uint32_t* b) {
    asm volatile(
        "mma.sync.aligned.m16n8k16.row.col.f32.f16.f16.f32 "
        "{%0,%1,%2,%3},{%4,%5,%6,%7},{%8,%9},{%0,%1,%2,%3};"
        : "+f"(c[0]), "+f"(c[1]), "+f"(c[2]), "+f"(c[3])
        : "r"(a[0]), "r"(a[1]), "r"(a[2]), "r"(a[3]),
          "r"(b[0]), "r"(b[1]));
}
__device__ __forceinline__ void ldsm_x4(uint32_t* r, uint32_t addr) {
    asm volatile("ldmatrix.sync.aligned.m8n8.x4.shared.b16 {%0,%1,%2,%3}, [%4];"
                 : "=r"(r[0]), "=r"(r[1]), "=r"(r[2]), "=r"(r[3]) : "r"(addr));
}
__device__ __forceinline__ void ldsm_x4_t(uint32_t* r, uint32_t addr) {
    asm volatile("ldmatrix.sync.aligned.m8n8.x4.trans.shared.b16 {%0,%1,%2,%3}, [%4];"
                 : "=r"(r[0]), "=r"(r[1]), "=r"(r[2]), "=r"(r[3]) : "r"(addr));
}
__device__ __forceinline__ uint32_t packh2(float a, float b) {
    __half2 h = __floats2half2_rn(a, b);
    return *(uint32_t*)&h;
}

// ---------------------------------------------------------------------------
// f32 -> f16 convert (n multiple of 8)
// ---------------------------------------------------------------------------
__global__ void __launch_bounds__(256) f32_to_f16(
    const float* __restrict__ in, __half* __restrict__ out, int n)
{
    int i = (blockIdx.x * 256 + threadIdx.x) * 8;
    if (i < n) {
        float4 a = *(const float4*)(in + i);
        float4 b = *(const float4*)(in + i + 4);
        __half2 h[4];
        h[0] = __floats2half2_rn(a.x, a.y);
        h[1] = __floats2half2_rn(a.z, a.w);
        h[2] = __floats2half2_rn(b.x, b.y);
        h[3] = __floats2half2_rn(b.z, b.w);
        *(uint4*)(out + i) = *(uint4*)h;
    }
}

// f32 [R][C] -> f16 transposed [C][R]
__global__ void __launch_bounds__(256) f32_to_f16_T(
    const float* __restrict__ in, __half* __restrict__ out, int R, int C)
{
    __shared__ float t[32][33];
    int bx = blockIdx.x * 32, by = blockIdx.y * 32;
    int x = threadIdx.x, y = threadIdx.y;   // 32 x 8
    #pragma unroll
    for (int i = 0; i < 32; i += 8)
        t[y + i][x] = in[(size_t)(by + y + i) * C + bx + x];
    __syncthreads();
    #pragma unroll
    for (int i = 0; i < 32; i += 8)
        out[(size_t)(bx + y + i) * R + by + x] = __float2half(t[x][y + i]);
}

// ---------------------------------------------------------------------------
// fp16 mma.sync GEMM (R11 winner, unchanged): C = A @ BT^T (+bias).
// 128x128 CTA, BK=32, 4 warps (2x2), warp tile 64x64, HST=40 smem rows.
// ---------------------------------------------------------------------------
#define HST 40   // halves per smem row

__global__ void __launch_bounds__(128, 2) gemm_f16(
    const __half* __restrict__ A, const __half* __restrict__ BT,
    const float* __restrict__ bias, void* __restrict__ Cout,
    int M, int N, int K, int out_half)
{
    __shared__ __half As[2][128 * HST];
    __shared__ __half Bs[2][128 * HST];

    const int tid  = threadIdx.x;
    const int lane = tid & 31;
    const int wid  = tid >> 5;
    const int wm   = wid & 1;
    const int wn   = wid >> 1;

    const long row0 = (long)blockIdx.y * 128;
    const long col0 = (long)blockIdx.x * 128;

    const __half* Ap = A  + (size_t)(row0 + tid) * K;
    const __half* Bp = BT + (size_t)(col0 + tid) * K;
    const uint32_t sts_off = (uint32_t)(tid * HST);

    const uint32_t as_b[2] = { smem_u32(As[0]), smem_u32(As[1]) };
    const uint32_t bs_b[2] = { smem_u32(Bs[0]), smem_u32(Bs[1]) };
    const uint32_t a_off = (uint32_t)((lane & 15) * HST + (lane >> 4) * 8) * 2;
    const uint32_t b_off = (uint32_t)(((lane & 7) + ((lane >> 4) << 3)) * HST
                                      + ((lane >> 3) & 1) * 8) * 2;

    float acc[4][8][4];
    #pragma unroll
    for (int mt = 0; mt < 4; mt++)
        #pragma unroll
        for (int nt = 0; nt < 8; nt++)
            #pragma unroll
            for (int i = 0; i < 4; i++) acc[mt][nt][i] = 0.f;

    uint4 pa[4], pb[4];
    #pragma unroll
    for (int j = 0; j < 4; j++) {
        pa[j] = *(const uint4*)(Ap + j * 8);
        pb[j] = *(const uint4*)(Bp + j * 8);
    }
    #pragma unroll
    for (int j = 0; j < 4; j++) {
        *(uint4*)&As[0][sts_off + j * 8] = pa[j];
        *(uint4*)&Bs[0][sts_off + j * 8] = pb[j];
    }
    __syncthreads();

    int buf = 0;
    for (int k0 = 0; k0 < K; k0 += 32) {
        const bool more = (k0 + 32 < K);
        if (more) {
            #pragma unroll
            for (int j = 0; j < 4; j++) {
                pa[j] = *(const uint4*)(Ap + k0 + 32 + j * 8);
                pb[j] = *(const uint4*)(Bp + k0 + 32 + j * 8);
            }
        }

        #pragma unroll
        for (int ks = 0; ks < 2; ks++) {
            uint32_t af[4][4];
            #pragma unroll
            for (int mt = 0; mt < 4; mt++)
                ldsm_x4(af[mt], as_b[buf]
                        + (uint32_t)((wm * 64 + mt * 16) * HST + ks * 16) * 2
                        + a_off);
            uint32_t bf[8][2];
            #pragma unroll
            for (int bg = 0; bg < 4; bg++) {
                uint32_t t[4];
                ldsm_x4(t, bs_b[buf]
                        + (uint32_t)((wn * 64 + bg * 16) * HST + ks * 16) * 2
                        + b_off);
                bf[bg * 2][0]     = t[0];
                bf[bg * 2][1]     = t[1];
                bf[bg * 2 + 1][0] = t[2];
                bf[bg * 2 + 1][1] = t[3];
            }
            #pragma unroll
            for (int mt = 0; mt < 4; mt++)
                #pragma unroll
                for (int nt = 0; nt < 8; nt++)
                    mma_f16(acc[mt][nt], af[mt], bf[nt]);
        }

        if (more) {
            const int nb = buf ^ 1;
            #pragma unroll
            for (int j = 0; j < 4; j++) {
                *(uint4*)&As[nb][sts_off + j * 8] = pa[j];
                *(uint4*)&Bs[nb][sts_off + j * 8] = pb[j];
            }
            __syncthreads();
            buf = nb;
        }
    }

    const int lq = lane >> 2;
    const int lr = lane & 3;
    if (out_half) {
        __half* Ch = (__half*)Cout;
        #pragma unroll
        for (int mt = 0; mt < 4; mt++) {
            long r0 = row0 + wm * 64 + mt * 16 + lq;
            #pragma unroll
            for (int nt = 0; nt < 8; nt++) {
                long c = col0 + wn * 64 + nt * 8 + 2 * lr;
                *(__half2*)(Ch + r0 * N + c) =
                    __floats2half2_rn(acc[mt][nt][0], acc[mt][nt][1]);
                *(__half2*)(Ch + (r0 + 8) * N + c) =
                    __floats2half2_rn(acc[mt][nt][2], acc[mt][nt][3]);
            }
        }
    } else {
        float* Cf = (float*)Cout;
        #pragma unroll
        for (int mt = 0; mt < 4; mt++) {
            long r0 = row0 + wm * 64 + mt * 16 + lq;
            #pragma unroll
            for (int nt = 0; nt < 8; nt++) {
                long c = col0 + wn * 64 + nt * 8 + 2 * lr;
                float bx = bias ? bias[c] : 0.f;
                float by = bias ? bias[c + 1] : 0.f;
                float2 v0, v1;
                v0.x = acc[mt][nt][0] + bx; v0.y = acc[mt][nt][1] + by;
                v1.x = acc[mt][nt][2] + bx; v1.y = acc[mt][nt][3] + by;
                *(float2*)(Cf + r0 * N + c)       = v0;
                *(float2*)(Cf + (r0 + 8) * N + c) = v1;
            }
        }
    }
}

// ---------------------------------------------------------------------------
// fp16 flash attention v3. CTA = 128 q-rows, 4 warps (128 thr), warp = 32
// q-rows (mt=2). REGISTER-DIRECT P: S accumulator fragments are packed
// straight into PV a-fragments (no P smem round-trip, no extra barrier).
// XOR-swizzled 128B smem rows; K via ldmatrix, V via ldmatrix.trans.
// ---------------------------------------------------------------------------
__global__ void __launch_bounds__(128, 2) flash_attn_f16(
    const __half* __restrict__ qkv, __half* __restrict__ out)
{
    __shared__ __half QP[128 * 64];   // Q staging (frags preloaded, then idle)
    __shared__ __half Ks[64 * 64];
    __shared__ __half Vs[64 * 64];

    const int tid  = threadIdx.x;
    const int lane = tid & 31;
    const int wid  = tid >> 5;       // 0..3
    const int lq   = lane >> 2;
    const int lr   = lane & 3;
    const int wr   = wid * 32;       // q-row base of this warp (32 rows)

    const int h  = blockIdx.y;
    const int b  = blockIdx.z;
    const int q0 = blockIdx.x * 128;

    const size_t base = (size_t)b * SEQ * QKV_N;
    const __half* qb = qkv + base + h * DHEAD;
    const __half* kb = qkv + base + DIMQ + h * DHEAD;
    const __half* vb = qkv + base + 2 * DIMQ + h * DHEAD;

    const uint32_t qp_b = smem_u32(QP);
    const uint32_t ks_b = smem_u32(Ks);
    const uint32_t vs_b = smem_u32(Vs);

    const float qscale = SCALE_A * LOG2E;

    // load Q tile (128 x 64), scale in f32, swizzled store (row = tid)
    {
        const int row = tid;
        const __half* qrow = qb + (size_t)(q0 + row) * QKV_N;
        #pragma unroll
        for (int c = 0; c < 8; c++) {
            uint4 u = *(const uint4*)(qrow + c * 8);
            __half2* hp = (__half2*)&u;
            #pragma unroll
            for (int e = 0; e < 4; e++) {
                float2 f = __half22float2(hp[e]);
                hp[e] = __floats2half2_rn(f.x * qscale, f.y * qscale);
            }
            const int pc = c ^ (row & 7);
            *(uint4*)&QP[row * 64 + pc * 8] = u;
        }
    }
    __syncthreads();

    // preload Q fragments: [mt][ks][4]
    uint32_t qf[2][4][4];
    {
        const int x = lane & 7;
        #pragma unroll
        for (int mt = 0; mt < 2; mt++) {
            const int arow = wr + mt * 16 + (lane & 15);
            #pragma unroll
            for (int ks = 0; ks < 4; ks++) {
                const int pc = (2 * ks + (lane >> 4)) ^ x;
                ldsm_x4(qf[mt][ks], qp_b + (uint32_t)(arow * 64 + pc * 8) * 2);
            }
        }
    }

    float o[2][8][4];
    #pragma unroll
    for (int mt = 0; mt < 2; mt++)
        #pragma unroll
        for (int nt = 0; nt < 8; nt++)
            #pragma unroll
            for (int i = 0; i < 4; i++) o[mt][nt][i] = 0.f;
    float mi[2][2], li[2][2];
    #pragma unroll
    for (int mt = 0; mt < 2; mt++) {
        mi[mt][0] = -1e30f; mi[mt][1] = -1e30f;
        li[mt][0] = 0.f;    li[mt][1] = 0.f;
    }

    for (int kt = 0; kt < SEQ; kt += 64) {
        // load K,V tile (64 rows x 8 chunks), swizzled
        #pragma unroll
        for (int it = 0; it < 4; it++) {
            const int row = (tid >> 3) + 16 * it;
            const int c   = tid & 7;
            const int pc  = c ^ (row & 7);
            *(uint4*)&Ks[row * 64 + pc * 8] =
                *(const uint4*)(kb + (size_t)(kt + row) * QKV_N + c * 8);
            *(uint4*)&Vs[row * 64 + pc * 8] =
                *(const uint4*)(vb + (size_t)(kt + row) * QKV_N + c * 8);
        }
        __syncthreads();

        // S = Q K^T : s[mt][nt][4]
        float s[2][8][4];
        #pragma unroll
        for (int mt = 0; mt < 2; mt++)
            #pragma unroll
            for (int nt = 0; nt < 8; nt++)
                #pragma unroll
                for (int i = 0; i < 4; i++) s[mt][nt][i] = 0.f;

        #pragma unroll
        for (int ks = 0; ks < 4; ks++) {
            uint32_t bf[8][2];
            #pragma unroll
            for (int bg = 0; bg < 4; bg++) {
                uint32_t t[4];
                const int row = bg * 16 + (lane & 7) + ((lane >> 4) << 3);
                const int pc  = (2 * ks + ((lane >> 3) & 1)) ^ (lane & 7);
                ldsm_x4(t, ks_b + (uint32_t)(row * 64 + pc * 8) * 2);
                bf[bg * 2][0]     = t[0];
                bf[bg * 2][1]     = t[1];
                bf[bg * 2 + 1][0] = t[2];
                bf[bg * 2 + 1][1] = t[3];
            }
            #pragma unroll
            for (int mt = 0; mt < 2; mt++)
                #pragma unroll
                for (int nt = 0; nt < 8; nt++)
                    mma_f16(s[mt][nt], qf[mt][ks], bf[nt]);
        }

        // online softmax per m-tile; exp2 domain
        #pragma unroll
        for (int mt = 0; mt < 2; mt++) {
            float mlo = -1e30f, mhi = -1e30f;
            #pragma unroll
            for (int nt = 0; nt < 8; nt++) {
                mlo = fmaxf(mlo, fmaxf(s[mt][nt][0], s[mt][nt][1]));
                mhi = fmaxf(mhi, fmaxf(s[mt][nt][2], s[mt][nt][3]));
            }
            mlo = fmaxf(mlo, __shfl_xor_sync(0xffffffffu, mlo, 1));
            mlo = fmaxf(mlo, __shfl_xor_sync(0xffffffffu, mlo, 2));
            mhi = fmaxf(mhi, __shfl_xor_sync(0xffffffffu, mhi, 1));
            mhi = fmaxf(mhi, __shfl_xor_sync(0xffffffffu, mhi, 2));

            const float mn_lo = fmaxf(mi[mt][0], mlo);
            const float mn_hi = fmaxf(mi[mt][1], mhi);
            const float corr_lo = exp2f(mi[mt][0] - mn_lo);
            const float corr_hi = exp2f(mi[mt][1] - mn_hi);
            mi[mt][0] = mn_lo; mi[mt][1] = mn_hi;

            float rs_lo = 0.f, rs_hi = 0.f;
            #pragma unroll
            for (int nt = 0; nt < 8; nt++) {
                s[mt][nt][0] = exp2f(s[mt][nt][0] - mn_lo);
                s[mt][nt][1] = exp2f(s[mt][nt][1] - mn_lo);
                s[mt][nt][2] = exp2f(s[mt][nt][2] - mn_hi);
                s[mt][nt][3] = exp2f(s[mt][nt][3] - mn_hi);
                rs_lo += s[mt][nt][0] + s[mt][nt][1];
                rs_hi += s[mt][nt][2] + s[mt][nt][3];
            }
            rs_lo += __shfl_xor_sync(0xffffffffu, rs_lo, 1);
            rs_lo += __shfl_xor_sync(0xffffffffu, rs_lo, 2);
            rs_hi += __shfl_xor_sync(0xffffffffu, rs_hi, 1);
            rs_hi += __shfl_xor_sync(0xffffffffu, rs_hi, 2);

            li[mt][0] = li[mt][0] * corr_lo + rs_lo;
            li[mt][1] = li[mt][1] * corr_hi + rs_hi;

            #pragma unroll
            for (int nt = 0; nt < 8; nt++) {
                o[mt][nt][0] *= corr_lo; o[mt][nt][1] *= corr_lo;
                o[mt][nt][2] *= corr_hi; o[mt][nt][3] *= corr_hi;
            }
        }

        // O += P @ V : P a-frags packed directly from S accumulators
        #pragma unroll
        for (int ks = 0; ks < 4; ks++) {
            uint32_t bfv[8][2];
            #pragma unroll
            for (int dt = 0; dt < 4; dt++) {
                uint32_t t[4];
                const int row = ks * 16 + (lane & 7) + ((lane >> 4) << 3);
                const int pc  = (2 * dt + ((lane >> 3) & 1)) ^ (lane & 7);
                ldsm_x4_t(t, vs_b + (uint32_t)(row * 64 + pc * 8) * 2);
                bfv[dt * 2][0]     = t[0];
                bfv[dt * 2][1]     = t[2];
                bfv[dt * 2 + 1][0] = t[1];
                bfv[dt * 2 + 1][1] = t[3];
            }
            #pragma unroll
            for (int mt = 0; mt < 2; mt++) {
                uint32_t ap[4];
                ap[0] = packh2(s[mt][2 * ks][0],     s[mt][2 * ks][1]);
                ap[1] = packh2(s[mt][2 * ks][2],     s[mt][2 * ks][3]);
                ap[2] = packh2(s[mt][2 * ks + 1][0], s[mt][2 * ks + 1][1]);
                ap[3] = packh2(s[mt][2 * ks + 1][2], s[mt][2 * ks + 1][3]);
                #pragma unroll
                for (int nt = 0; nt < 8; nt++)
                    mma_f16(o[mt][nt], ap, bfv[nt]);
            }
        }
        __syncthreads();   // protect Ks/Vs before next tile load
    }

    // epilogue: normalize, fp16 out
    __half* ob = out + ((size_t)b * SEQ + q0) * DIMQ + h * DHEAD;
    #pragma unroll
    for (int mt = 0; mt < 2; mt++) {
        const float inv_lo = 1.f / li[mt][0];
        const float inv_hi = 1.f / li[mt][1];
        const int m = wr + mt * 16 + lq;
        #pragma unroll
        for (int nt = 0; nt < 8; nt++) {
            const int col = nt * 8 + 2 * lr;
            *(__half2*)(ob + (size_t)m * DIMQ + col) =
                __floats2half2_rn(o[mt][nt][0] * inv_lo, o[mt][nt][1] * inv_lo);
            *(__half2*)(ob + (size_t)(m + 8) * DIMQ + col) =
                __floats2half2_rn(o[mt][nt][2] * inv_hi, o[mt][nt][3] * inv_hi);
        }
    }
}

// ---------------------------------------------------------------------------
// Launch
// ---------------------------------------------------------------------------
extern "C" void kernel_launch(void* const* d_in, const int* in_sizes, int n_in,
                              void* d_out, int out_size)
{
    const float* x    = (const float*)d_in[0];   // [2,2048,1024]
    const float* Wqkv = (const float*)d_in[1];   // [1024,3072]
    const float* Wout = (const float*)d_in[2];   // [1024,1024]
    const float* bout = (const float*)d_in[3];   // [1024]
    float* out = (float*)d_out;                  // [2,2048,1024] f32

    __half *qkv, *att, *xh, *wqkvT, *woutT;
    cudaGetSymbolAddress((void**)&qkv, g_qkv);
    cudaGetSymbolAddress((void**)&att, g_att);
    cudaGetSymbolAddress((void**)&xh, g_xh);
    cudaGetSymbolAddress((void**)&wqkvT, g_wqkvT);
    cudaGetSymbolAddress((void**)&woutT, g_woutT);

    // Stage 0: convert x to fp16; convert+transpose weights to [n][k] fp16
    {
        int nx = NTOK * DIMQ;
        f32_to_f16<<<nx / 8 / 256, 256>>>(x, xh, nx);
        f32_to_f16_T<<<dim3(QKV_N / 32, DIMQ / 32), dim3(32, 8)>>>(
            Wqkv, wqkvT, DIMQ, QKV_N);
        f32_to_f16_T<<<dim3(DIMQ / 32, DIMQ / 32), dim3(32, 8)>>>(
            Wout, woutT, DIMQ, DIMQ);
    }

    // Stage 1: qkv = x @ W_qkv  (4096 x 3072 x 1024), fp16 out
    {
        dim3 grid(QKV_N / 128, NTOK / 128);
        gemm_f16<<<grid, 128>>>(xh, wqkvT, nullptr, qkv, NTOK, QKV_N, DIMQ, 1);
    }

    // Stage 2: flash attention (128 q-rows per CTA, 4 warps), fp16 out
    {
        dim3 grid(SEQ / 128, HEADS, BATCH);
        flash_attn_f16<<<grid, 128>>>(qkv, att);
    }

    // Stage 3: out = att @ W_out + b_out  (4096 x 1024 x 1024), f32 out
    {
        dim3 grid(DIMQ / 128, NTOK / 128);
        gemm_f16<<<grid, 128>>>(att, woutT, bout, out, NTOK, DIMQ, DIMQ, 0);
    }
}

// round 13
// speedup vs baseline: 1.9295x; 1.0217x over previous
#include <cuda_runtime.h>
#include <cuda_fp16.h>
#include <math.h>
#include <stdint.h>

#define DIMQ     1024
#define HEADS    16
#define DHEAD    64
#define SEQ      2048
#define BATCH    2
#define NTOK     (BATCH * SEQ)      // 4096
#define QKV_N    (3 * DIMQ)         // 3072
#define SCALE_A  0.125f             // 1/sqrt(64)
#define LOG2E    1.4426950408889634f

// Scratch (static device globals — allocation-free)
__device__ __half g_qkv[(size_t)NTOK * QKV_N];   // Q|K|V fp16
__device__ __half g_att[(size_t)NTOK * DIMQ];    // attention result fp16
__device__ __half g_xh[(size_t)NTOK * DIMQ];     // x fp16 [m][k]
__device__ __half g_wqkvT[(size_t)QKV_N * DIMQ]; // W_qkv^T fp16 [n][k]
__device__ __half g_woutT[(size_t)DIMQ * DIMQ];  // W_out^T fp16 [n][k]

// ---------------------------------------------------------------------------
// helpers
// ---------------------------------------------------------------------------
__device__ __forceinline__ uint32_t smem_u32(const void* p) {
    uint32_t a;
    asm("{ .reg .u64 t; cvta.to.shared.u64 t, %1; cvt.u32.u64 %0, t; }"
        : "=r"(a) : "l"(p));
    return a;
}
__device__ __forceinline__ void mma_f16(float* c, const uint32_t* a, const uint32_t* b) {
    asm volatile(
        "mma.sync.aligned.m16n8k16.row.col.f32.f16.f16.f32 "
        "{%0,%1,%2,%3},{%4,%5,%6,%7},{%8,%9},{%0,%1,%2,%3};"
        : "+f"(c[0]), "+f"(c[1]), "+f"(c[2]), "+f"(c[3])
        : "r"(a[0]), "r"(a[1]), "r"(a[2]), "r"(a[3]),
          "r"(b[0]), "r"(b[1]));
}
__device__ __forceinline__ void ldsm_x4(uint32_t* r, uint32_t addr) {
    asm volatile("ldmatrix.sync.aligned.m8n8.x4.shared.b16 {%0,%1,%2,%3}, [%4];"
                 : "=r"(r[0]), "=r"(r[1]), "=r"(r[2]), "=r"(r[3]) : "r"(addr));
}
__device__ __forceinline__ void ldsm_x4_t(uint32_t* r, uint32_t addr) {
    asm volatile("ldmatrix.sync.aligned.m8n8.x4.trans.shared.b16 {%0,%1,%2,%3}, [%4];"
                 : "=r"(r[0]), "=r"(r[1]), "=r"(r[2]), "=r"(r[3]) : "r"(addr));
}
__device__ __forceinline__ uint32_t packh2(float a, float b) {
    __half2 h = __floats2half2_rn(a, b);
    return *(uint32_t*)&h;
}
__device__ __forceinline__ void cp16(uint32_t dst, const void* src) {
    asm volatile("cp.async.cg.shared.global [%0], [%1], 16;"
                 :: "r"(dst), "l"(src) : "memory");
}
#define CP_COMMIT() asm volatile("cp.async.commit_group;" ::: "memory")
#define CP_WAIT_0() asm volatile("cp.async.wait_group 0;" ::: "memory")

// ---------------------------------------------------------------------------
// f32 -> f16 convert (n multiple of 8)
// ---------------------------------------------------------------------------
__global__ void __launch_bounds__(256) f32_to_f16(
    const float* __restrict__ in, __half* __restrict__ out, int n)
{
    int i = (blockIdx.x * 256 + threadIdx.x) * 8;
    if (i < n) {
        float4 a = *(const float4*)(in + i);
        float4 b = *(const float4*)(in + i + 4);
        __half2 h[4];
        h[0] = __floats2half2_rn(a.x, a.y);
        h[1] = __floats2half2_rn(a.z, a.w);
        h[2] = __floats2half2_rn(b.x, b.y);
        h[3] = __floats2half2_rn(b.z, b.w);
        *(uint4*)(out + i) = *(uint4*)h;
    }
}

// f32 [R][C] -> f16 transposed [C][R]
__global__ void __launch_bounds__(256) f32_to_f16_T(
    const float* __restrict__ in, __half* __restrict__ out, int R, int C)
{
    __shared__ float t[32][33];
    int bx = blockIdx.x * 32, by = blockIdx.y * 32;
    int x = threadIdx.x, y = threadIdx.y;   // 32 x 8
    #pragma unroll
    for (int i = 0; i < 32; i += 8)
        t[y + i][x] = in[(size_t)(by + y + i) * C + bx + x];
    __syncthreads();
    #pragma unroll
    for (int i = 0; i < 32; i += 8)
        out[(size_t)(bx + y + i) * R + by + x] = __float2half(t[x][y + i]);
}

// ---------------------------------------------------------------------------
// fp16 mma.sync GEMM v3: C = A @ BT^T (+bias). 128x128 CTA, BK=64,
// 128 threads = 4 warps (2x2), warp tile 64x64. cp.async double-buffered
// (wait->sync->issue->compute ordering: race-free with 2 buffers).
// smem rows HST2=72 halves (144B; LDSM bank walk 4r mod 32 conflict-free).
// Dynamic smem 73728 B. out_half -> fp16 C else f32 (+bias).
// ---------------------------------------------------------------------------
#define HST2 72
#define GEMM_SMEM (4 * 128 * HST2 * 2)   // 73728 bytes

__global__ void __launch_bounds__(128, 2) gemm_f16(
    const __half* __restrict__ A, const __half* __restrict__ BT,
    const float* __restrict__ bias, void* __restrict__ Cout,
    int M, int N, int K, int out_half)
{
    extern __shared__ __half smh[];
    // layout: As0 | As1 | Bs0 | Bs1, each 128*HST2 halves
    const uint32_t sb = smem_u32(smh);
    const uint32_t as_b[2] = { sb, sb + 128 * HST2 * 2 };
    const uint32_t bs_b[2] = { sb + 2 * 128 * HST2 * 2, sb + 3 * 128 * HST2 * 2 };

    const int tid  = threadIdx.x;
    const int lane = tid & 31;
    const int wid  = tid >> 5;
    const int wm   = wid & 1;
    const int wn   = wid >> 1;

    const long row0 = (long)blockIdx.y * 128;
    const long col0 = (long)blockIdx.x * 128;

    const __half* Ap = A  + (size_t)(row0 + tid) * K;
    const __half* Bp = BT + (size_t)(col0 + tid) * K;
    const uint32_t sts_off = (uint32_t)(tid * HST2) * 2;   // byte offset

    const uint32_t a_off = (uint32_t)((lane & 15) * HST2 + (lane >> 4) * 8) * 2;
    const uint32_t b_off = (uint32_t)(((lane & 7) + ((lane >> 4) << 3)) * HST2
                                      + ((lane >> 3) & 1) * 8) * 2;

    float acc[4][8][4];
    #pragma unroll
    for (int mt = 0; mt < 4; mt++)
        #pragma unroll
        for (int nt = 0; nt < 8; nt++)
            #pragma unroll
            for (int i = 0; i < 4; i++) acc[mt][nt][i] = 0.f;

    const int NC = K / 64;

    // prologue: chunk 0 -> buffer 0
    #pragma unroll
    for (int j = 0; j < 8; j++) {
        cp16(as_b[0] + sts_off + j * 16, Ap + j * 8);
        cp16(bs_b[0] + sts_off + j * 16, Bp + j * 8);
    }
    CP_COMMIT();

    for (int c = 0; c < NC; c++) {
        const int buf = c & 1;
        CP_WAIT_0();          // chunk c landed
        __syncthreads();      // orders prior compute before new cp writes

        if (c + 1 < NC) {
            const int nb = buf ^ 1;
            const long kc = (long)(c + 1) * 64;
            #pragma unroll
            for (int j = 0; j < 8; j++) {
                cp16(as_b[nb] + sts_off + j * 16, Ap + kc + j * 8);
                cp16(bs_b[nb] + sts_off + j * 16, Bp + kc + j * 8);
            }
            CP_COMMIT();
        }

        // compute on buf: 4 k16-steps, warp tile 64x64
        #pragma unroll
        for (int ks = 0; ks < 4; ks++) {
            uint32_t af[4][4];
            #pragma unroll
            for (int mt = 0; mt < 4; mt++)
                ldsm_x4(af[mt], as_b[buf]
                        + (uint32_t)((wm * 64 + mt * 16) * HST2 + ks * 16) * 2
                        + a_off);
            uint32_t bf[8][2];
            #pragma unroll
            for (int bg = 0; bg < 4; bg++) {
                uint32_t t[4];
                ldsm_x4(t, bs_b[buf]
                        + (uint32_t)((wn * 64 + bg * 16) * HST2 + ks * 16) * 2
                        + b_off);
                bf[bg * 2][0]     = t[0];
                bf[bg * 2][1]     = t[1];
                bf[bg * 2 + 1][0] = t[2];
                bf[bg * 2 + 1][1] = t[3];
            }
            #pragma unroll
            for (int mt = 0; mt < 4; mt++)
                #pragma unroll
                for (int nt = 0; nt < 8; nt++)
                    mma_f16(acc[mt][nt], af[mt], bf[nt]);
        }
    }

    // epilogue: acc rows lq/lq+8, cols 2lr/2lr+1 per n-tile
    const int lq = lane >> 2;
    const int lr = lane & 3;
    if (out_half) {
        __half* Ch = (__half*)Cout;
        #pragma unroll
        for (int mt = 0; mt < 4; mt++) {
            long r0 = row0 + wm * 64 + mt * 16 + lq;
            #pragma unroll
            for (int nt = 0; nt < 8; nt++) {
                long c = col0 + wn * 64 + nt * 8 + 2 * lr;
                *(__half2*)(Ch + r0 * N + c) =
                    __floats2half2_rn(acc[mt][nt][0], acc[mt][nt][1]);
                *(__half2*)(Ch + (r0 + 8) * N + c) =
                    __floats2half2_rn(acc[mt][nt][2], acc[mt][nt][3]);
            }
        }
    } else {
        float* Cf = (float*)Cout;
        #pragma unroll
        for (int mt = 0; mt < 4; mt++) {
            long r0 = row0 + wm * 64 + mt * 16 + lq;
            #pragma unroll
            for (int nt = 0; nt < 8; nt++) {
                long c = col0 + wn * 64 + nt * 8 + 2 * lr;
                float bx = bias ? bias[c] : 0.f;
                float by = bias ? bias[c + 1] : 0.f;
                float2 v0, v1;
                v0.x = acc[mt][nt][0] + bx; v0.y = acc[mt][nt][1] + by;
                v1.x = acc[mt][nt][2] + bx; v1.y = acc[mt][nt][3] + by;
                *(float2*)(Cf + r0 * N + c)       = v0;
                *(float2*)(Cf + (r0 + 8) * N + c) = v1;
            }
        }
    }
}

// ---------------------------------------------------------------------------
// fp16 flash attention v3 (R12 winner, unchanged). CTA = 128 q-rows,
// 4 warps, warp = 32 q-rows. Register-direct P; XOR-swizzled smem;
// K via ldmatrix, V via ldmatrix.trans.
// ---------------------------------------------------------------------------
__global__ void __launch_bounds__(128, 2) flash_attn_f16(
    const __half* __restrict__ qkv, __half* __restrict__ out)
{
    __shared__ __half QP[128 * 64];
    __shared__ __half Ks[64 * 64];
    __shared__ __half Vs[64 * 64];

    const int tid  = threadIdx.x;
    const int lane = tid & 31;
    const int wid  = tid >> 5;
    const int lq   = lane >> 2;
    const int lr   = lane & 3;
    const int wr   = wid * 32;

    const int h  = blockIdx.y;
    const int b  = blockIdx.z;
    const int q0 = blockIdx.x * 128;

    const size_t base = (size_t)b * SEQ * QKV_N;
    const __half* qb = qkv + base + h * DHEAD;
    const __half* kb = qkv + base + DIMQ + h * DHEAD;
    const __half* vb = qkv + base + 2 * DIMQ + h * DHEAD;

    const uint32_t qp_b = smem_u32(QP);
    const uint32_t ks_b = smem_u32(Ks);
    const uint32_t vs_b = smem_u32(Vs);

    const float qscale = SCALE_A * LOG2E;

    {
        const int row = tid;
        const __half* qrow = qb + (size_t)(q0 + row) * QKV_N;
        #pragma unroll
        for (int c = 0; c < 8; c++) {
            uint4 u = *(const uint4*)(qrow + c * 8);
            __half2* hp = (__half2*)&u;
            #pragma unroll
            for (int e = 0; e < 4; e++) {
                float2 f = __half22float2(hp[e]);
                hp[e] = __floats2half2_rn(f.x * qscale, f.y * qscale);
            }
            const int pc = c ^ (row & 7);
            *(uint4*)&QP[row * 64 + pc * 8] = u;
        }
    }
    __syncthreads();

    uint32_t qf[2][4][4];
    {
        const int x = lane & 7;
        #pragma unroll
        for (int mt = 0; mt < 2; mt++) {
            const int arow = wr + mt * 16 + (lane & 15);
            #pragma unroll
            for (int ks = 0; ks < 4; ks++) {
                const int pc = (2 * ks + (lane >> 4)) ^ x;
                ldsm_x4(qf[mt][ks], qp_b + (uint32_t)(arow * 64 + pc * 8) * 2);
            }
        }
    }

    float o[2][8][4];
    #pragma unroll
    for (int mt = 0; mt < 2; mt++)
        #pragma unroll
        for (int nt = 0; nt < 8; nt++)
            #pragma unroll
            for (int i = 0; i < 4; i++) o[mt][nt][i] = 0.f;
    float mi[2][2], li[2][2];
    #pragma unroll
    for (int mt = 0; mt < 2; mt++) {
        mi[mt][0] = -1e30f; mi[mt][1] = -1e30f;
        li[mt][0] = 0.f;    li[mt][1] = 0.f;
    }

    for (int kt = 0; kt < SEQ; kt += 64) {
        #pragma unroll
        for (int it = 0; it < 4; it++) {
            const int row = (tid >> 3) + 16 * it;
            const int c   = tid & 7;
            const int pc  = c ^ (row & 7);
            *(uint4*)&Ks[row * 64 + pc * 8] =
                *(const uint4*)(kb + (size_t)(kt + row) * QKV_N + c * 8);
            *(uint4*)&Vs[row * 64 + pc * 8] =
                *(const uint4*)(vb + (size_t)(kt + row) * QKV_N + c * 8);
        }
        __syncthreads();

        float s[2][8][4];
        #pragma unroll
        for (int mt = 0; mt < 2; mt++)
            #pragma unroll
            for (int nt = 0; nt < 8; nt++)
                #pragma unroll
                for (int i = 0; i < 4; i++) s[mt][nt][i] = 0.f;

        #pragma unroll
        for (int ks = 0; ks < 4; ks++) {
            uint32_t bf[8][2];
            #pragma unroll
            for (int bg = 0; bg < 4; bg++) {
                uint32_t t[4];
                const int row = bg * 16 + (lane & 7) + ((lane >> 4) << 3);
                const int pc  = (2 * ks + ((lane >> 3) & 1)) ^ (lane & 7);
                ldsm_x4(t, ks_b + (uint32_t)(row * 64 + pc * 8) * 2);
                bf[bg * 2][0]     = t[0];
                bf[bg * 2][1]     = t[1];
                bf[bg * 2 + 1][0] = t[2];
                bf[bg * 2 + 1][1] = t[3];
            }
            #pragma unroll
            for (int mt = 0; mt < 2; mt++)
                #pragma unroll
                for (int nt = 0; nt < 8; nt++)
                    mma_f16(s[mt][nt], qf[mt][ks], bf[nt]);
        }

        #pragma unroll
        for (int mt = 0; mt < 2; mt++) {
            float mlo = -1e30f, mhi = -1e30f;
            #pragma unroll
            for (int nt = 0; nt < 8; nt++) {
                mlo = fmaxf(mlo, fmaxf(s[mt][nt][0], s[mt][nt][1]));
                mhi = fmaxf(mhi, fmaxf(s[mt][nt][2], s[mt][nt][3]));
            }
            mlo = fmaxf(mlo, __shfl_xor_sync(0xffffffffu, mlo, 1));
            mlo = fmaxf(mlo, __shfl_xor_sync(0xffffffffu, mlo, 2));
            mhi = fmaxf(mhi, __shfl_xor_sync(0xffffffffu, mhi, 1));
            mhi = fmaxf(mhi, __shfl_xor_sync(0xffffffffu, mhi, 2));

            const float mn_lo = fmaxf(mi[mt][0], mlo);
            const float mn_hi = fmaxf(mi[mt][1], mhi);
            const float corr_lo = exp2f(mi[mt][0] - mn_lo);
            const float corr_hi = exp2f(mi[mt][1] - mn_hi);
            mi[mt][0] = mn_lo; mi[mt][1] = mn_hi;

            float rs_lo = 0.f, rs_hi = 0.f;
            #pragma unroll
            for (int nt = 0; nt < 8; nt++) {
                s[mt][nt][0] = exp2f(s[mt][nt][0] - mn_lo);
                s[mt][nt][1] = exp2f(s[mt][nt][1] - mn_lo);
                s[mt][nt][2] = exp2f(s[mt][nt][2] - mn_hi);
                s[mt][nt][3] = exp2f(s[mt][nt][3] - mn_hi);
                rs_lo += s[mt][nt][0] + s[mt][nt][1];
                rs_hi += s[mt][nt][2] + s[mt][nt][3];
            }
            rs_lo += __shfl_xor_sync(0xffffffffu, rs_lo, 1);
            rs_lo += __shfl_xor_sync(0xffffffffu, rs_lo, 2);
            rs_hi += __shfl_xor_sync(0xffffffffu, rs_hi, 1);
            rs_hi += __shfl_xor_sync(0xffffffffu, rs_hi, 2);

            li[mt][0] = li[mt][0] * corr_lo + rs_lo;
            li[mt][1] = li[mt][1] * corr_hi + rs_hi;

            #pragma unroll
            for (int nt = 0; nt < 8; nt++) {
                o[mt][nt][0] *= corr_lo; o[mt][nt][1] *= corr_lo;
                o[mt][nt][2] *= corr_hi; o[mt][nt][3] *= corr_hi;
            }
        }

        #pragma unroll
        for (int ks = 0; ks < 4; ks++) {
            uint32_t bfv[8][2];
            #pragma unroll
            for (int dt = 0; dt < 4; dt++) {
                uint32_t t[4];
                const int row = ks * 16 + (lane & 7) + ((lane >> 4) << 3);
                const int pc  = (2 * dt + ((lane >> 3) & 1)) ^ (lane & 7);
                ldsm_x4_t(t, vs_b + (uint32_t)(row * 64 + pc * 8) * 2);
                bfv[dt * 2][0]     = t[0];
                bfv[dt * 2][1]     = t[2];
                bfv[dt * 2 + 1][0] = t[1];
                bfv[dt * 2 + 1][1] = t[3];
            }
            #pragma unroll
            for (int mt = 0; mt < 2; mt++) {
                uint32_t ap[4];
                ap[0] = packh2(s[mt][2 * ks][0],     s[mt][2 * ks][1]);
                ap[1] = packh2(s[mt][2 * ks][2],     s[mt][2 * ks][3]);
                ap[2] = packh2(s[mt][2 * ks + 1][0], s[mt][2 * ks + 1][1]);
                ap[3] = packh2(s[mt][2 * ks + 1][2], s[mt][2 * ks + 1][3]);
                #pragma unroll
                for (int nt = 0; nt < 8; nt++)
                    mma_f16(o[mt][nt], ap, bfv[nt]);
            }
        }
        __syncthreads();
    }

    __half* ob = out + ((size_t)b * SEQ + q0) * DIMQ + h * DHEAD;
    #pragma unroll
    for (int mt = 0; mt < 2; mt++) {
        const float inv_lo = 1.f / li[mt][0];
        const float inv_hi = 1.f / li[mt][1];
        const int m = wr + mt * 16 + lq;
        #pragma unroll
        for (int nt = 0; nt < 8; nt++) {
            const int col = nt * 8 + 2 * lr;
            *(__half2*)(ob + (size_t)m * DIMQ + col) =
                __floats2half2_rn(o[mt][nt][0] * inv_lo, o[mt][nt][1] * inv_lo);
            *(__half2*)(ob + (size_t)(m + 8) * DIMQ + col) =
                __floats2half2_rn(o[mt][nt][2] * inv_hi, o[mt][nt][3] * inv_hi);
        }
    }
}

// ---------------------------------------------------------------------------
// Launch
// ---------------------------------------------------------------------------
extern "C" void kernel_launch(void* const* d_in, const int* in_sizes, int n_in,
                              void* d_out, int out_size)
{
    const float* x    = (const float*)d_in[0];   // [2,2048,1024]
    const float* Wqkv = (const float*)d_in[1];   // [1024,3072]
    const float* Wout = (const float*)d_in[2];   // [1024,1024]
    const float* bout = (const float*)d_in[3];   // [1024]
    float* out = (float*)d_out;                  // [2,2048,1024] f32

    __half *qkv, *att, *xh, *wqkvT, *woutT;
    cudaGetSymbolAddress((void**)&qkv, g_qkv);
    cudaGetSymbolAddress((void**)&att, g_att);
    cudaGetSymbolAddress((void**)&xh, g_xh);
    cudaGetSymbolAddress((void**)&wqkvT, g_wqkvT);
    cudaGetSymbolAddress((void**)&woutT, g_woutT);

    cudaFuncSetAttribute(gemm_f16,
                         cudaFuncAttributeMaxDynamicSharedMemorySize, GEMM_SMEM);

    // Stage 0: convert x to fp16; convert+transpose weights to [n][k] fp16
    {
        int nx = NTOK * DIMQ;
        f32_to_f16<<<nx / 8 / 256, 256>>>(x, xh, nx);
        f32_to_f16_T<<<dim3(QKV_N / 32, DIMQ / 32), dim3(32, 8)>>>(
            Wqkv, wqkvT, DIMQ, QKV_N);
        f32_to_f16_T<<<dim3(DIMQ / 32, DIMQ / 32), dim3(32, 8)>>>(
            Wout, woutT, DIMQ, DIMQ);
    }

    // Stage 1: qkv = x @ W_qkv  (4096 x 3072 x 1024), fp16 out
    {
        dim3 grid(QKV_N / 128, NTOK / 128);
        gemm_f16<<<grid, 128, GEMM_SMEM>>>(xh, wqkvT, nullptr, qkv,
                                           NTOK, QKV_N, DIMQ, 1);
    }

    // Stage 2: flash attention (128 q-rows per CTA, 4 warps), fp16 out
    {
        dim3 grid(SEQ / 128, HEADS, BATCH);
        flash_attn_f16<<<grid, 128>>>(qkv, att);
    }

    // Stage 3: out = att @ W_out + b_out  (4096 x 1024 x 1024), f32 out
    {
        dim3 grid(DIMQ / 128, NTOK / 128);
        gemm_f16<<<grid, 128, GEMM_SMEM>>>(att, woutT, bout, out,
                                           NTOK, DIMQ, DIMQ, 0);
    }
}

// round 14
// speedup vs baseline: 2.0922x; 1.0843x over previous
#include <cuda_runtime.h>
#include <cuda_fp16.h>
#include <math.h>
#include <stdint.h>

#define DIMQ     1024
#define HEADS    16
#define DHEAD    64
#define SEQ      2048
#define BATCH    2
#define NTOK     (BATCH * SEQ)      // 4096
#define QKV_N    (3 * DIMQ)         // 3072
#define SCALE_A  0.125f             // 1/sqrt(64)
#define LOG2E    1.4426950408889634f

// Scratch (static device globals — allocation-free)
__device__ __half g_qkv[(size_t)NTOK * QKV_N];   // Q|K|V fp16
__device__ __half g_att[(size_t)NTOK * DIMQ];    // attention result fp16
__device__ __half g_xh[(size_t)NTOK * DIMQ];     // x fp16 [m][k]
__device__ __half g_wqkvT[(size_t)QKV_N * DIMQ]; // W_qkv^T fp16 [n][k]
__device__ __half g_woutT[(size_t)DIMQ * DIMQ];  // W_out^T fp16 [n][k]

// ---------------------------------------------------------------------------
// helpers
// ---------------------------------------------------------------------------
__device__ __forceinline__ uint32_t smem_u32(const void* p) {
    uint32_t a;
    asm("{ .reg .u64 t; cvta.to.shared.u64 t, %1; cvt.u32.u64 %0, t; }"
        : "=r"(a) : "l"(p));
    return a;
}
__device__ __forceinline__ void mma_f16(float* c, const uint32_t* a, const uint32_t* b) {
    asm volatile(
        "mma.sync.aligned.m16n8k16.row.col.f32.f16.f16.f32 "
        "{%0,%1,%2,%3},{%4,%5,%6,%7},{%8,%9},{%0,%1,%2,%3};"
        : "+f"(c[0]), "+f"(c[1]), "+f"(c[2]), "+f"(c[3])
        : "r"(a[0]), "r"(a[1]), "r"(a[2]), "r"(a[3]),
          "r"(b[0]), "r"(b[1]));
}
__device__ __forceinline__ void ldsm_x4(uint32_t* r, uint32_t addr) {
    asm volatile("ldmatrix.sync.aligned.m8n8.x4.shared.b16 {%0,%1,%2,%3}, [%4];"
                 : "=r"(r[0]), "=r"(r[1]), "=r"(r[2]), "=r"(r[3]) : "r"(addr));
}
__device__ __forceinline__ void ldsm_x4_t(uint32_t* r, uint32_t addr) {
    asm volatile("ldmatrix.sync.aligned.m8n8.x4.trans.shared.b16 {%0,%1,%2,%3}, [%4];"
                 : "=r"(r[0]), "=r"(r[1]), "=r"(r[2]), "=r"(r[3]) : "r"(addr));
}
__device__ __forceinline__ uint32_t packh2(float a, float b) {
    __half2 h = __floats2half2_rn(a, b);
    return *(uint32_t*)&h;
}
__device__ __forceinline__ void cp16(uint32_t dst, const void* src) {
    asm volatile("cp.async.cg.shared.global [%0], [%1], 16;"
                 :: "r"(dst), "l"(src) : "memory");
}
#define CP_COMMIT() asm volatile("cp.async.commit_group;" ::: "memory")
#define CP_WAIT(n)  asm volatile("cp.async.wait_group %0;" :: "n"(n) : "memory")

// ---------------------------------------------------------------------------
// f32 -> f16 convert (n multiple of 8)
// ---------------------------------------------------------------------------
__global__ void __launch_bounds__(256) f32_to_f16(
    const float* __restrict__ in, __half* __restrict__ out, int n)
{
    int i = (blockIdx.x * 256 + threadIdx.x) * 8;
    if (i < n) {
        float4 a = *(const float4*)(in + i);
        float4 b = *(const float4*)(in + i + 4);
        __half2 h[4];
        h[0] = __floats2half2_rn(a.x, a.y);
        h[1] = __floats2half2_rn(a.z, a.w);
        h[2] = __floats2half2_rn(b.x, b.y);
        h[3] = __floats2half2_rn(b.z, b.w);
        *(uint4*)(out + i) = *(uint4*)h;
    }
}

// f32 [R][C] -> f16 transposed [C][R]
__global__ void __launch_bounds__(256) f32_to_f16_T(
    const float* __restrict__ in, __half* __restrict__ out, int R, int C)
{
    __shared__ float t[32][33];
    int bx = blockIdx.x * 32, by = blockIdx.y * 32;
    int x = threadIdx.x, y = threadIdx.y;   // 32 x 8
    #pragma unroll
    for (int i = 0; i < 32; i += 8)
        t[y + i][x] = in[(size_t)(by + y + i) * C + bx + x];
    __syncthreads();
    #pragma unroll
    for (int i = 0; i < 32; i += 8)
        out[(size_t)(bx + y + i) * R + by + x] = __float2half(t[x][y + i]);
}

// ---------------------------------------------------------------------------
// fp16 mma.sync GEMM v4: C = A @ BT^T (+bias). 128x128 CTA, BK=32,
// 4 warps (2x2), warp tile 64x64. 4-STAGE cp.async pipeline (wait_group 2:
// 2-3 chunks in flight — hides L2 latency/bandwidth draw).
// smem rows HST=40 halves (80B; LDSM bank starts {0,20,8,28,16,4,24,12}
// partition all 32 banks: conflict-free). Dynamic smem 81920 B.
// ---------------------------------------------------------------------------
#define HST 40
#define NSTAGE 4
#define STG_HALVES (128 * HST)
#define GEMM_SMEM (2 * NSTAGE * STG_HALVES * 2)   // 81920 bytes

__global__ void __launch_bounds__(128, 2) gemm_f16(
    const __half* __restrict__ A, const __half* __restrict__ BT,
    const float* __restrict__ bias, void* __restrict__ Cout,
    int M, int N, int K, int out_half)
{
    extern __shared__ __half smh[];
    const uint32_t sb = smem_u32(smh);
    // layout: As[0..3] | Bs[0..3]
    uint32_t as_b[NSTAGE], bs_b[NSTAGE];
    #pragma unroll
    for (int s = 0; s < NSTAGE; s++) {
        as_b[s] = sb + (uint32_t)(s * STG_HALVES) * 2;
        bs_b[s] = sb + (uint32_t)((NSTAGE + s) * STG_HALVES) * 2;
    }

    const int tid  = threadIdx.x;
    const int lane = tid & 31;
    const int wid  = tid >> 5;
    const int wm   = wid & 1;
    const int wn   = wid >> 1;

    const long row0 = (long)blockIdx.y * 128;
    const long col0 = (long)blockIdx.x * 128;

    const __half* Ap = A  + (size_t)(row0 + tid) * K;
    const __half* Bp = BT + (size_t)(col0 + tid) * K;
    const uint32_t sts_off = (uint32_t)(tid * HST) * 2;   // byte offset

    const uint32_t a_off = (uint32_t)((lane & 15) * HST + (lane >> 4) * 8) * 2;
    const uint32_t b_off = (uint32_t)(((lane & 7) + ((lane >> 4) << 3)) * HST
                                      + ((lane >> 3) & 1) * 8) * 2;

    float acc[4][8][4];
    #pragma unroll
    for (int mt = 0; mt < 4; mt++)
        #pragma unroll
        for (int nt = 0; nt < 8; nt++)
            #pragma unroll
            for (int i = 0; i < 4; i++) acc[mt][nt][i] = 0.f;

    const int NC = K / 32;

    // prologue: issue chunks 0..2 into stages 0..2
    #pragma unroll
    for (int s = 0; s < 3; s++) {
        const long kc = (long)s * 32;
        #pragma unroll
        for (int j = 0; j < 4; j++) {
            cp16(as_b[s] + sts_off + j * 16, Ap + kc + j * 8);
            cp16(bs_b[s] + sts_off + j * 16, Bp + kc + j * 8);
        }
        CP_COMMIT();
    }

    for (int c = 0; c < NC; c++) {
        const int buf = c & (NSTAGE - 1);
        CP_WAIT(2);           // chunk c landed (c+1, c+2 may still fly)
        __syncthreads();      // all warps done with chunk c-1's buffer reads

        if (c + 3 < NC) {
            const int nb = (c + 3) & (NSTAGE - 1);
            const long kc = (long)(c + 3) * 32;
            #pragma unroll
            for (int j = 0; j < 4; j++) {
                cp16(as_b[nb] + sts_off + j * 16, Ap + kc + j * 8);
                cp16(bs_b[nb] + sts_off + j * 16, Bp + kc + j * 8);
            }
            CP_COMMIT();
        }

        // compute chunk c: 2 k16-steps, warp tile 64x64
        #pragma unroll
        for (int ks = 0; ks < 2; ks++) {
            uint32_t af[4][4];
            #pragma unroll
            for (int mt = 0; mt < 4; mt++)
                ldsm_x4(af[mt], as_b[buf]
                        + (uint32_t)((wm * 64 + mt * 16) * HST + ks * 16) * 2
                        + a_off);
            uint32_t bf[8][2];
            #pragma unroll
            for (int bg = 0; bg < 4; bg++) {
                uint32_t t[4];
                ldsm_x4(t, bs_b[buf]
                        + (uint32_t)((wn * 64 + bg * 16) * HST + ks * 16) * 2
                        + b_off);
                bf[bg * 2][0]     = t[0];
                bf[bg * 2][1]     = t[1];
                bf[bg * 2 + 1][0] = t[2];
                bf[bg * 2 + 1][1] = t[3];
            }
            #pragma unroll
            for (int mt = 0; mt < 4; mt++)
                #pragma unroll
                for (int nt = 0; nt < 8; nt++)
                    mma_f16(acc[mt][nt], af[mt], bf[nt]);
        }
    }

    // epilogue: acc rows lq/lq+8, cols 2lr/2lr+1 per n-tile
    const int lq = lane >> 2;
    const int lr = lane & 3;
    if (out_half) {
        __half* Ch = (__half*)Cout;
        #pragma unroll
        for (int mt = 0; mt < 4; mt++) {
            long r0 = row0 + wm * 64 + mt * 16 + lq;
            #pragma unroll
            for (int nt = 0; nt < 8; nt++) {
                long c = col0 + wn * 64 + nt * 8 + 2 * lr;
                *(__half2*)(Ch + r0 * N + c) =
                    __floats2half2_rn(acc[mt][nt][0], acc[mt][nt][1]);
                *(__half2*)(Ch + (r0 + 8) * N + c) =
                    __floats2half2_rn(acc[mt][nt][2], acc[mt][nt][3]);
            }
        }
    } else {
        float* Cf = (float*)Cout;
        #pragma unroll
        for (int mt = 0; mt < 4; mt++) {
            long r0 = row0 + wm * 64 + mt * 16 + lq;
            #pragma unroll
            for (int nt = 0; nt < 8; nt++) {
                long c = col0 + wn * 64 + nt * 8 + 2 * lr;
                float bx = bias ? bias[c] : 0.f;
                float by = bias ? bias[c + 1] : 0.f;
                float2 v0, v1;
                v0.x = acc[mt][nt][0] + bx; v0.y = acc[mt][nt][1] + by;
                v1.x = acc[mt][nt][2] + bx; v1.y = acc[mt][nt][3] + by;
                *(float2*)(Cf + r0 * N + c)       = v0;
                *(float2*)(Cf + (r0 + 8) * N + c) = v1;
            }
        }
    }
}

// ---------------------------------------------------------------------------
// fp16 flash attention v3 (R12 winner, unchanged). CTA = 128 q-rows,
// 4 warps, warp = 32 q-rows. Register-direct P; XOR-swizzled smem;
// K via ldmatrix, V via ldmatrix.trans.
// ---------------------------------------------------------------------------
__global__ void __launch_bounds__(128, 2) flash_attn_f16(
    const __half* __restrict__ qkv, __half* __restrict__ out)
{
    __shared__ __half QP[128 * 64];
    __shared__ __half Ks[64 * 64];
    __shared__ __half Vs[64 * 64];

    const int tid  = threadIdx.x;
    const int lane = tid & 31;
    const int wid  = tid >> 5;
    const int lq   = lane >> 2;
    const int lr   = lane & 3;
    const int wr   = wid * 32;

    const int h  = blockIdx.y;
    const int b  = blockIdx.z;
    const int q0 = blockIdx.x * 128;

    const size_t base = (size_t)b * SEQ * QKV_N;
    const __half* qb = qkv + base + h * DHEAD;
    const __half* kb = qkv + base + DIMQ + h * DHEAD;
    const __half* vb = qkv + base + 2 * DIMQ + h * DHEAD;

    const uint32_t qp_b = smem_u32(QP);
    const uint32_t ks_b = smem_u32(Ks);
    const uint32_t vs_b = smem_u32(Vs);

    const float qscale = SCALE_A * LOG2E;

    {
        const int row = tid;
        const __half* qrow = qb + (size_t)(q0 + row) * QKV_N;
        #pragma unroll
        for (int c = 0; c < 8; c++) {
            uint4 u = *(const uint4*)(qrow + c * 8);
            __half2* hp = (__half2*)&u;
            #pragma unroll
            for (int e = 0; e < 4; e++) {
                float2 f = __half22float2(hp[e]);
                hp[e] = __floats2half2_rn(f.x * qscale, f.y * qscale);
            }
            const int pc = c ^ (row & 7);
            *(uint4*)&QP[row * 64 + pc * 8] = u;
        }
    }
    __syncthreads();

    uint32_t qf[2][4][4];
    {
        const int x = lane & 7;
        #pragma unroll
        for (int mt = 0; mt < 2; mt++) {
            const int arow = wr + mt * 16 + (lane & 15);
            #pragma unroll
            for (int ks = 0; ks < 4; ks++) {
                const int pc = (2 * ks + (lane >> 4)) ^ x;
                ldsm_x4(qf[mt][ks], qp_b + (uint32_t)(arow * 64 + pc * 8) * 2);
            }
        }
    }

    float o[2][8][4];
    #pragma unroll
    for (int mt = 0; mt < 2; mt++)
        #pragma unroll
        for (int nt = 0; nt < 8; nt++)
            #pragma unroll
            for (int i = 0; i < 4; i++) o[mt][nt][i] = 0.f;
    float mi[2][2], li[2][2];
    #pragma unroll
    for (int mt = 0; mt < 2; mt++) {
        mi[mt][0] = -1e30f; mi[mt][1] = -1e30f;
        li[mt][0] = 0.f;    li[mt][1] = 0.f;
    }

    for (int kt = 0; kt < SEQ; kt += 64) {
        #pragma unroll
        for (int it = 0; it < 4; it++) {
            const int row = (tid >> 3) + 16 * it;
            const int c   = tid & 7;
            const int pc  = c ^ (row & 7);
            *(uint4*)&Ks[row * 64 + pc * 8] =
                *(const uint4*)(kb + (size_t)(kt + row) * QKV_N + c * 8);
            *(uint4*)&Vs[row * 64 + pc * 8] =
                *(const uint4*)(vb + (size_t)(kt + row) * QKV_N + c * 8);
        }
        __syncthreads();

        float s[2][8][4];
        #pragma unroll
        for (int mt = 0; mt < 2; mt++)
            #pragma unroll
            for (int nt = 0; nt < 8; nt++)
                #pragma unroll
                for (int i = 0; i < 4; i++) s[mt][nt][i] = 0.f;

        #pragma unroll
        for (int ks = 0; ks < 4; ks++) {
            uint32_t bf[8][2];
            #pragma unroll
            for (int bg = 0; bg < 4; bg++) {
                uint32_t t[4];
                const int row = bg * 16 + (lane & 7) + ((lane >> 4) << 3);
                const int pc  = (2 * ks + ((lane >> 3) & 1)) ^ (lane & 7);
                ldsm_x4(t, ks_b + (uint32_t)(row * 64 + pc * 8) * 2);
                bf[bg * 2][0]     = t[0];
                bf[bg * 2][1]     = t[1];
                bf[bg * 2 + 1][0] = t[2];
                bf[bg * 2 + 1][1] = t[3];
            }
            #pragma unroll
            for (int mt = 0; mt < 2; mt++)
                #pragma unroll
                for (int nt = 0; nt < 8; nt++)
                    mma_f16(s[mt][nt], qf[mt][ks], bf[nt]);
        }

        #pragma unroll
        for (int mt = 0; mt < 2; mt++) {
            float mlo = -1e30f, mhi = -1e30f;
            #pragma unroll
            for (int nt = 0; nt < 8; nt++) {
                mlo = fmaxf(mlo, fmaxf(s[mt][nt][0], s[mt][nt][1]));
                mhi = fmaxf(mhi, fmaxf(s[mt][nt][2], s[mt][nt][3]));
            }
            mlo = fmaxf(mlo, __shfl_xor_sync(0xffffffffu, mlo, 1));
            mlo = fmaxf(mlo, __shfl_xor_sync(0xffffffffu, mlo, 2));
            mhi = fmaxf(mhi, __shfl_xor_sync(0xffffffffu, mhi, 1));
            mhi = fmaxf(mhi, __shfl_xor_sync(0xffffffffu, mhi, 2));

            const float mn_lo = fmaxf(mi[mt][0], mlo);
            const float mn_hi = fmaxf(mi[mt][1], mhi);
            const float corr_lo = exp2f(mi[mt][0] - mn_lo);
            const float corr_hi = exp2f(mi[mt][1] - mn_hi);
            mi[mt][0] = mn_lo; mi[mt][1] = mn_hi;

            float rs_lo = 0.f, rs_hi = 0.f;
            #pragma unroll
            for (int nt = 0; nt < 8; nt++) {
                s[mt][nt][0] = exp2f(s[mt][nt][0] - mn_lo);
                s[mt][nt][1] = exp2f(s[mt][nt][1] - mn_lo);
                s[mt][nt][2] = exp2f(s[mt][nt][2] - mn_hi);
                s[mt][nt][3] = exp2f(s[mt][nt][3] - mn_hi);
                rs_lo += s[mt][nt][0] + s[mt][nt][1];
                rs_hi += s[mt][nt][2] + s[mt][nt][3];
            }
            rs_lo += __shfl_xor_sync(0xffffffffu, rs_lo, 1);
            rs_lo += __shfl_xor_sync(0xffffffffu, rs_lo, 2);
            rs_hi += __shfl_xor_sync(0xffffffffu, rs_hi, 1);
            rs_hi += __shfl_xor_sync(0xffffffffu, rs_hi, 2);

            li[mt][0] = li[mt][0] * corr_lo + rs_lo;
            li[mt][1] = li[mt][1] * corr_hi + rs_hi;

            #pragma unroll
            for (int nt = 0; nt < 8; nt++) {
                o[mt][nt][0] *= corr_lo; o[mt][nt][1] *= corr_lo;
                o[mt][nt][2] *= corr_hi; o[mt][nt][3] *= corr_hi;
            }
        }

        #pragma unroll
        for (int ks = 0; ks < 4; ks++) {
            uint32_t bfv[8][2];
            #pragma unroll
            for (int dt = 0; dt < 4; dt++) {
                uint32_t t[4];
                const int row = ks * 16 + (lane & 7) + ((lane >> 4) << 3);
                const int pc  = (2 * dt + ((lane >> 3) & 1)) ^ (lane & 7);
                ldsm_x4_t(t, vs_b + (uint32_t)(row * 64 + pc * 8) * 2);
                bfv[dt * 2][0]     = t[0];
                bfv[dt * 2][1]     = t[2];
                bfv[dt * 2 + 1][0] = t[1];
                bfv[dt * 2 + 1][1] = t[3];
            }
            #pragma unroll
            for (int mt = 0; mt < 2; mt++) {
                uint32_t ap[4];
                ap[0] = packh2(s[mt][2 * ks][0],     s[mt][2 * ks][1]);
                ap[1] = packh2(s[mt][2 * ks][2],     s[mt][2 * ks][3]);
                ap[2] = packh2(s[mt][2 * ks + 1][0], s[mt][2 * ks + 1][1]);
                ap[3] = packh2(s[mt][2 * ks + 1][2], s[mt][2 * ks + 1][3]);
                #pragma unroll
                for (int nt = 0; nt < 8; nt++)
                    mma_f16(o[mt][nt], ap, bfv[nt]);
            }
        }
        __syncthreads();
    }

    __half* ob = out + ((size_t)b * SEQ + q0) * DIMQ + h * DHEAD;
    #pragma unroll
    for (int mt = 0; mt < 2; mt++) {
        const float inv_lo = 1.f / li[mt][0];
        const float inv_hi = 1.f / li[mt][1];
        const int m = wr + mt * 16 + lq;
        #pragma unroll
        for (int nt = 0; nt < 8; nt++) {
            const int col = nt * 8 + 2 * lr;
            *(__half2*)(ob + (size_t)m * DIMQ + col) =
                __floats2half2_rn(o[mt][nt][0] * inv_lo, o[mt][nt][1] * inv_lo);
            *(__half2*)(ob + (size_t)(m + 8) * DIMQ + col) =
                __floats2half2_rn(o[mt][nt][2] * inv_hi, o[mt][nt][3] * inv_hi);
        }
    }
}

// ---------------------------------------------------------------------------
// Launch
// ---------------------------------------------------------------------------
extern "C" void kernel_launch(void* const* d_in, const int* in_sizes, int n_in,
                              void* d_out, int out_size)
{
    const float* x    = (const float*)d_in[0];   // [2,2048,1024]
    const float* Wqkv = (const float*)d_in[1];   // [1024,3072]
    const float* Wout = (const float*)d_in[2];   // [1024,1024]
    const float* bout = (const float*)d_in[3];   // [1024]
    float* out = (float*)d_out;                  // [2,2048,1024] f32

    __half *qkv, *att, *xh, *wqkvT, *woutT;
    cudaGetSymbolAddress((void**)&qkv, g_qkv);
    cudaGetSymbolAddress((void**)&att, g_att);
    cudaGetSymbolAddress((void**)&xh, g_xh);
    cudaGetSymbolAddress((void**)&wqkvT, g_wqkvT);
    cudaGetSymbolAddress((void**)&woutT, g_woutT);

    cudaFuncSetAttribute(gemm_f16,
                         cudaFuncAttributeMaxDynamicSharedMemorySize, GEMM_SMEM);

    // Stage 0: convert x to fp16; convert+transpose weights to [n][k] fp16
    {
        int nx = NTOK * DIMQ;
        f32_to_f16<<<nx / 8 / 256, 256>>>(x, xh, nx);
        f32_to_f16_T<<<dim3(QKV_N / 32, DIMQ / 32), dim3(32, 8)>>>(
            Wqkv, wqkvT, DIMQ, QKV_N);
        f32_to_f16_T<<<dim3(DIMQ / 32, DIMQ / 32), dim3(32, 8)>>>(
            Wout, woutT, DIMQ, DIMQ);
    }

    // Stage 1: qkv = x @ W_qkv  (4096 x 3072 x 1024), fp16 out
    {
        dim3 grid(QKV_N / 128, NTOK / 128);
        gemm_f16<<<grid, 128, GEMM_SMEM>>>(xh, wqkvT, nullptr, qkv,
                                           NTOK, QKV_N, DIMQ, 1);
    }

    // Stage 2: flash attention (128 q-rows per CTA, 4 warps), fp16 out
    {
        dim3 grid(SEQ / 128, HEADS, BATCH);
        flash_attn_f16<<<grid, 128>>>(qkv, att);
    }

    // Stage 3: out = att @ W_out + b_out  (4096 x 1024 x 1024), f32 out
    {
        dim3 grid(DIMQ / 128, NTOK / 128);
        gemm_f16<<<grid, 128, GEMM_SMEM>>>(att, woutT, bout, out,
                                           NTOK, DIMQ, DIMQ, 0);
    }
}

// round 15
// speedup vs baseline: 2.2067x; 1.0547x over previous
#include <cuda_runtime.h>
#include <cuda_fp16.h>
#include <math.h>
#include <stdint.h>

#define DIMQ     1024
#define HEADS    16
#define DHEAD    64
#define SEQ      2048
#define BATCH    2
#define NTOK     (BATCH * SEQ)      // 4096
#define QKV_N    (3 * DIMQ)         // 3072
#define SCALE_A  0.125f             // 1/sqrt(64)
#define LOG2E    1.4426950408889634f

// Scratch (static device globals — allocation-free)
__device__ __half g_qkv[(size_t)NTOK * QKV_N];   // Q|K|V fp16
__device__ __half g_att[(size_t)NTOK * DIMQ];    // attention result fp16
__device__ __half g_xh[(size_t)NTOK * DIMQ];     // x fp16 [m][k]
__device__ __half g_wqkvT[(size_t)QKV_N * DIMQ]; // W_qkv^T fp16 [n][k]
__device__ __half g_woutT[(size_t)DIMQ * DIMQ];  // W_out^T fp16 [n][k]

// ---------------------------------------------------------------------------
// helpers
// ---------------------------------------------------------------------------
__device__ __forceinline__ uint32_t smem_u32(const void* p) {
    uint32_t a;
    asm("{ .reg .u64 t; cvta.to.shared.u64 t, %1; cvt.u32.u64 %0, t; }"
        : "=r"(a) : "l"(p));
    return a;
}
__device__ __forceinline__ void mma_f16(float* c, const uint32_t* a, const uint32_t* b) {
    asm volatile(
        "mma.sync.aligned.m16n8k16.row.col.f32.f16.f16.f32 "
        "{%0,%1,%2,%3},{%4,%5,%6,%7},{%8,%9},{%0,%1,%2,%3};"
        : "+f"(c[0]), "+f"(c[1]), "+f"(c[2]), "+f"(c[3])
        : "r"(a[0]), "r"(a[1]), "r"(a[2]), "r"(a[3]),
          "r"(b[0]), "r"(b[1]));
}
__device__ __forceinline__ void ldsm_x4(uint32_t* r, uint32_t addr) {
    asm volatile("ldmatrix.sync.aligned.m8n8.x4.shared.b16 {%0,%1,%2,%3}, [%4];"
                 : "=r"(r[0]), "=r"(r[1]), "=r"(r[2]), "=r"(r[3]) : "r"(addr));
}
__device__ __forceinline__ void ldsm_x4_t(uint32_t* r, uint32_t addr) {
    asm volatile("ldmatrix.sync.aligned.m8n8.x4.trans.shared.b16 {%0,%1,%2,%3}, [%4];"
                 : "=r"(r[0]), "=r"(r[1]), "=r"(r[2]), "=r"(r[3]) : "r"(addr));
}
__device__ __forceinline__ uint32_t packh2(float a, float b) {
    __half2 h = __floats2half2_rn(a, b);
    return *(uint32_t*)&h;
}
__device__ __forceinline__ void cp16(uint32_t dst, const void* src) {
    asm volatile("cp.async.cg.shared.global [%0], [%1], 16;"
                 :: "r"(dst), "l"(src) : "memory");
}
#define CP_COMMIT() asm volatile("cp.async.commit_group;" ::: "memory")
#define CP_WAIT(n)  asm volatile("cp.async.wait_group %0;" :: "n"(n) : "memory")

// ---------------------------------------------------------------------------
// f32 -> f16 convert (n multiple of 8)
// ---------------------------------------------------------------------------
__global__ void __launch_bounds__(256) f32_to_f16(
    const float* __restrict__ in, __half* __restrict__ out, int n)
{
    int i = (blockIdx.x * 256 + threadIdx.x) * 8;
    if (i < n) {
        float4 a = *(const float4*)(in + i);
        float4 b = *(const float4*)(in + i + 4);
        __half2 h[4];
        h[0] = __floats2half2_rn(a.x, a.y);
        h[1] = __floats2half2_rn(a.z, a.w);
        h[2] = __floats2half2_rn(b.x, b.y);
        h[3] = __floats2half2_rn(b.z, b.w);
        *(uint4*)(out + i) = *(uint4*)h;
    }
}

// f32 [R][C] -> f16 transposed [C][R]
__global__ void __launch_bounds__(256) f32_to_f16_T(
    const float* __restrict__ in, __half* __restrict__ out, int R, int C)
{
    __shared__ float t[32][33];
    int bx = blockIdx.x * 32, by = blockIdx.y * 32;
    int x = threadIdx.x, y = threadIdx.y;   // 32 x 8
    #pragma unroll
    for (int i = 0; i < 32; i += 8)
        t[y + i][x] = in[(size_t)(by + y + i) * C + bx + x];
    __syncthreads();
    #pragma unroll
    for (int i = 0; i < 32; i += 8)
        out[(size_t)(bx + y + i) * R + by + x] = __float2half(t[x][y + i]);
}

// ---------------------------------------------------------------------------
// fp16 mma.sync GEMM v4 (R14 winner, unchanged): C = A @ BT^T (+bias).
// 128x128 CTA, BK=32, 4 warps (2x2), warp tile 64x64. 4-stage cp.async.
// ---------------------------------------------------------------------------
#define HST 40
#define NSTAGE 4
#define STG_HALVES (128 * HST)
#define GEMM_SMEM (2 * NSTAGE * STG_HALVES * 2)   // 81920 bytes

__global__ void __launch_bounds__(128, 2) gemm_f16(
    const __half* __restrict__ A, const __half* __restrict__ BT,
    const float* __restrict__ bias, void* __restrict__ Cout,
    int M, int N, int K, int out_half)
{
    extern __shared__ __half smh[];
    const uint32_t sb = smem_u32(smh);
    uint32_t as_b[NSTAGE], bs_b[NSTAGE];
    #pragma unroll
    for (int s = 0; s < NSTAGE; s++) {
        as_b[s] = sb + (uint32_t)(s * STG_HALVES) * 2;
        bs_b[s] = sb + (uint32_t)((NSTAGE + s) * STG_HALVES) * 2;
    }

    const int tid  = threadIdx.x;
    const int lane = tid & 31;
    const int wid  = tid >> 5;
    const int wm   = wid & 1;
    const int wn   = wid >> 1;

    const long row0 = (long)blockIdx.y * 128;
    const long col0 = (long)blockIdx.x * 128;

    const __half* Ap = A  + (size_t)(row0 + tid) * K;
    const __half* Bp = BT + (size_t)(col0 + tid) * K;
    const uint32_t sts_off = (uint32_t)(tid * HST) * 2;

    const uint32_t a_off = (uint32_t)((lane & 15) * HST + (lane >> 4) * 8) * 2;
    const uint32_t b_off = (uint32_t)(((lane & 7) + ((lane >> 4) << 3)) * HST
                                      + ((lane >> 3) & 1) * 8) * 2;

    float acc[4][8][4];
    #pragma unroll
    for (int mt = 0; mt < 4; mt++)
        #pragma unroll
        for (int nt = 0; nt < 8; nt++)
            #pragma unroll
            for (int i = 0; i < 4; i++) acc[mt][nt][i] = 0.f;

    const int NC = K / 32;

    #pragma unroll
    for (int s = 0; s < 3; s++) {
        const long kc = (long)s * 32;
        #pragma unroll
        for (int j = 0; j < 4; j++) {
            cp16(as_b[s] + sts_off + j * 16, Ap + kc + j * 8);
            cp16(bs_b[s] + sts_off + j * 16, Bp + kc + j * 8);
        }
        CP_COMMIT();
    }

    for (int c = 0; c < NC; c++) {
        const int buf = c & (NSTAGE - 1);
        CP_WAIT(2);
        __syncthreads();

        if (c + 3 < NC) {
            const int nb = (c + 3) & (NSTAGE - 1);
            const long kc = (long)(c + 3) * 32;
            #pragma unroll
            for (int j = 0; j < 4; j++) {
                cp16(as_b[nb] + sts_off + j * 16, Ap + kc + j * 8);
                cp16(bs_b[nb] + sts_off + j * 16, Bp + kc + j * 8);
            }
            CP_COMMIT();
        }

        #pragma unroll
        for (int ks = 0; ks < 2; ks++) {
            uint32_t af[4][4];
            #pragma unroll
            for (int mt = 0; mt < 4; mt++)
                ldsm_x4(af[mt], as_b[buf]
                        + (uint32_t)((wm * 64 + mt * 16) * HST + ks * 16) * 2
                        + a_off);
            uint32_t bf[8][2];
            #pragma unroll
            for (int bg = 0; bg < 4; bg++) {
                uint32_t t[4];
                ldsm_x4(t, bs_b[buf]
                        + (uint32_t)((wn * 64 + bg * 16) * HST + ks * 16) * 2
                        + b_off);
                bf[bg * 2][0]     = t[0];
                bf[bg * 2][1]     = t[1];
                bf[bg * 2 + 1][0] = t[2];
                bf[bg * 2 + 1][1] = t[3];
            }
            #pragma unroll
            for (int mt = 0; mt < 4; mt++)
                #pragma unroll
                for (int nt = 0; nt < 8; nt++)
                    mma_f16(acc[mt][nt], af[mt], bf[nt]);
        }
    }

    const int lq = lane >> 2;
    const int lr = lane & 3;
    if (out_half) {
        __half* Ch = (__half*)Cout;
        #pragma unroll
        for (int mt = 0; mt < 4; mt++) {
            long r0 = row0 + wm * 64 + mt * 16 + lq;
            #pragma unroll
            for (int nt = 0; nt < 8; nt++) {
                long c = col0 + wn * 64 + nt * 8 + 2 * lr;
                *(__half2*)(Ch + r0 * N + c) =
                    __floats2half2_rn(acc[mt][nt][0], acc[mt][nt][1]);
                *(__half2*)(Ch + (r0 + 8) * N + c) =
                    __floats2half2_rn(acc[mt][nt][2], acc[mt][nt][3]);
            }
        }
    } else {
        float* Cf = (float*)Cout;
        #pragma unroll
        for (int mt = 0; mt < 4; mt++) {
            long r0 = row0 + wm * 64 + mt * 16 + lq;
            #pragma unroll
            for (int nt = 0; nt < 8; nt++) {
                long c = col0 + wn * 64 + nt * 8 + 2 * lr;
                float bx = bias ? bias[c] : 0.f;
                float by = bias ? bias[c + 1] : 0.f;
                float2 v0, v1;
                v0.x = acc[mt][nt][0] + bx; v0.y = acc[mt][nt][1] + by;
                v1.x = acc[mt][nt][2] + bx; v1.y = acc[mt][nt][3] + by;
                *(float2*)(Cf + r0 * N + c)       = v0;
                *(float2*)(Cf + (r0 + 8) * N + c) = v1;
            }
        }
    }
}

// ---------------------------------------------------------------------------
// fp16 flash attention v4: R12 compute structure + 3-STAGE cp.async K/V
// pipeline (one barrier per key-tile). CTA = 128 q-rows, 4 warps, warp = 32
// q-rows, register-direct P, XOR-swizzled smem.
// Dynamic smem layout (halves): QP[8192] | K0|K1|K2 (4096 each) | V0|V1|V2.
// ---------------------------------------------------------------------------
#define FA_STG 3
#define FA_SMEM ((8192 + 6 * 4096) * 2)   // 65536 bytes

__global__ void __launch_bounds__(128, 2) flash_attn_f16(
    const __half* __restrict__ qkv, __half* __restrict__ out)
{
    extern __shared__ __half fsm[];
    const uint32_t sb = smem_u32(fsm);
    const uint32_t qp_b = sb;
    uint32_t ks_b[FA_STG], vs_b[FA_STG];
    #pragma unroll
    for (int s = 0; s < FA_STG; s++) {
        ks_b[s] = sb + (uint32_t)(8192 + s * 4096) * 2;
        vs_b[s] = sb + (uint32_t)(8192 + (3 + s) * 4096) * 2;
    }
    __half* QP = fsm;

    const int tid  = threadIdx.x;
    const int lane = tid & 31;
    const int wid  = tid >> 5;
    const int lq   = lane >> 2;
    const int lr   = lane & 3;
    const int wr   = wid * 32;

    const int h  = blockIdx.y;
    const int b  = blockIdx.z;
    const int q0 = blockIdx.x * 128;

    const size_t base = (size_t)b * SEQ * QKV_N;
    const __half* qb = qkv + base + h * DHEAD;
    const __half* kb = qkv + base + DIMQ + h * DHEAD;
    const __half* vb = qkv + base + 2 * DIMQ + h * DHEAD;

    const float qscale = SCALE_A * LOG2E;

    // K/V tile copy mapping: thread -> 4 rows x 1 chunk, swizzled dst
    const int cp_c   = tid & 7;                 // chunk 0..7
    const int cp_r0  = tid >> 3;                // row 0..15 (+16*it)

    // issue one K/V tile into stage s (kt = key-tile base row)
    auto issue_tile = [&](int kt, int s) {
        #pragma unroll
        for (int it = 0; it < 4; it++) {
            const int row = cp_r0 + 16 * it;
            const int pc  = cp_c ^ (row & 7);
            const uint32_t doff = (uint32_t)(row * 64 + pc * 8) * 2;
            cp16(ks_b[s] + doff,
                 kb + (size_t)(kt + row) * QKV_N + cp_c * 8);
            cp16(vs_b[s] + doff,
                 vb + (size_t)(kt + row) * QKV_N + cp_c * 8);
        }
        CP_COMMIT();
    };

    // prologue: issue key-tiles 0 and 1
    issue_tile(0, 0);
    issue_tile(64, 1);

    // load Q tile (overlaps with in-flight K/V), scale in f32, swizzled
    {
        const int row = tid;
        const __half* qrow = qb + (size_t)(q0 + row) * QKV_N;
        #pragma unroll
        for (int c = 0; c < 8; c++) {
            uint4 u = *(const uint4*)(qrow + c * 8);
            __half2* hp = (__half2*)&u;
            #pragma unroll
            for (int e = 0; e < 4; e++) {
                float2 f = __half22float2(hp[e]);
                hp[e] = __floats2half2_rn(f.x * qscale, f.y * qscale);
            }
            const int pc = c ^ (row & 7);
            *(uint4*)&QP[row * 64 + pc * 8] = u;
        }
    }
    __syncthreads();

    uint32_t qf[2][4][4];
    {
        const int x = lane & 7;
        #pragma unroll
        for (int mt = 0; mt < 2; mt++) {
            const int arow = wr + mt * 16 + (lane & 15);
            #pragma unroll
            for (int ks = 0; ks < 4; ks++) {
                const int pc = (2 * ks + (lane >> 4)) ^ x;
                ldsm_x4(qf[mt][ks], qp_b + (uint32_t)(arow * 64 + pc * 8) * 2);
            }
        }
    }

    float o[2][8][4];
    #pragma unroll
    for (int mt = 0; mt < 2; mt++)
        #pragma unroll
        for (int nt = 0; nt < 8; nt++)
            #pragma unroll
            for (int i = 0; i < 4; i++) o[mt][nt][i] = 0.f;
    float mi[2][2], li[2][2];
    #pragma unroll
    for (int mt = 0; mt < 2; mt++) {
        mi[mt][0] = -1e30f; mi[mt][1] = -1e30f;
        li[mt][0] = 0.f;    li[mt][1] = 0.f;
    }

    const int NT = SEQ / 64;   // 32 key tiles
    int buf = 0;
    for (int t = 0; t < NT; t++) {
        CP_WAIT(1);           // tile t landed (t+1 may fly)
        __syncthreads();      // all warps done with tile t-1's buffer

        if (t + 2 < NT)
            issue_tile((t + 2) * 64, (t + 2) % FA_STG);

        const uint32_t kbuf = ks_b[buf];
        const uint32_t vbuf = vs_b[buf];

        // S = Q K^T
        float s[2][8][4];
        #pragma unroll
        for (int mt = 0; mt < 2; mt++)
            #pragma unroll
            for (int nt = 0; nt < 8; nt++)
                #pragma unroll
                for (int i = 0; i < 4; i++) s[mt][nt][i] = 0.f;

        #pragma unroll
        for (int ks = 0; ks < 4; ks++) {
            uint32_t bf[8][2];
            #pragma unroll
            for (int bg = 0; bg < 4; bg++) {
                uint32_t t4[4];
                const int row = bg * 16 + (lane & 7) + ((lane >> 4) << 3);
                const int pc  = (2 * ks + ((lane >> 3) & 1)) ^ (lane & 7);
                ldsm_x4(t4, kbuf + (uint32_t)(row * 64 + pc * 8) * 2);
                bf[bg * 2][0]     = t4[0];
                bf[bg * 2][1]     = t4[1];
                bf[bg * 2 + 1][0] = t4[2];
                bf[bg * 2 + 1][1] = t4[3];
            }
            #pragma unroll
            for (int mt = 0; mt < 2; mt++)
                #pragma unroll
                for (int nt = 0; nt < 8; nt++)
                    mma_f16(s[mt][nt], qf[mt][ks], bf[nt]);
        }

        // online softmax (exp2 domain)
        #pragma unroll
        for (int mt = 0; mt < 2; mt++) {
            float mlo = -1e30f, mhi = -1e30f;
            #pragma unroll
            for (int nt = 0; nt < 8; nt++) {
                mlo = fmaxf(mlo, fmaxf(s[mt][nt][0], s[mt][nt][1]));
                mhi = fmaxf(mhi, fmaxf(s[mt][nt][2], s[mt][nt][3]));
            }
            mlo = fmaxf(mlo, __shfl_xor_sync(0xffffffffu, mlo, 1));
            mlo = fmaxf(mlo, __shfl_xor_sync(0xffffffffu, mlo, 2));
            mhi = fmaxf(mhi, __shfl_xor_sync(0xffffffffu, mhi, 1));
            mhi = fmaxf(mhi, __shfl_xor_sync(0xffffffffu, mhi, 2));

            const float mn_lo = fmaxf(mi[mt][0], mlo);
            const float mn_hi = fmaxf(mi[mt][1], mhi);
            const float corr_lo = exp2f(mi[mt][0] - mn_lo);
            const float corr_hi = exp2f(mi[mt][1] - mn_hi);
            mi[mt][0] = mn_lo; mi[mt][1] = mn_hi;

            float rs_lo = 0.f, rs_hi = 0.f;
            #pragma unroll
            for (int nt = 0; nt < 8; nt++) {
                s[mt][nt][0] = exp2f(s[mt][nt][0] - mn_lo);
                s[mt][nt][1] = exp2f(s[mt][nt][1] - mn_lo);
                s[mt][nt][2] = exp2f(s[mt][nt][2] - mn_hi);
                s[mt][nt][3] = exp2f(s[mt][nt][3] - mn_hi);
                rs_lo += s[mt][nt][0] + s[mt][nt][1];
                rs_hi += s[mt][nt][2] + s[mt][nt][3];
            }
            rs_lo += __shfl_xor_sync(0xffffffffu, rs_lo, 1);
            rs_lo += __shfl_xor_sync(0xffffffffu, rs_lo, 2);
            rs_hi += __shfl_xor_sync(0xffffffffu, rs_hi, 1);
            rs_hi += __shfl_xor_sync(0xffffffffu, rs_hi, 2);

            li[mt][0] = li[mt][0] * corr_lo + rs_lo;
            li[mt][1] = li[mt][1] * corr_hi + rs_hi;

            #pragma unroll
            for (int nt = 0; nt < 8; nt++) {
                o[mt][nt][0] *= corr_lo; o[mt][nt][1] *= corr_lo;
                o[mt][nt][2] *= corr_hi; o[mt][nt][3] *= corr_hi;
            }
        }

        // O += P @ V (register-direct P)
        #pragma unroll
        for (int ks = 0; ks < 4; ks++) {
            uint32_t bfv[8][2];
            #pragma unroll
            for (int dt = 0; dt < 4; dt++) {
                uint32_t t4[4];
                const int row = ks * 16 + (lane & 7) + ((lane >> 4) << 3);
                const int pc  = (2 * dt + ((lane >> 3) & 1)) ^ (lane & 7);
                ldsm_x4_t(t4, vbuf + (uint32_t)(row * 64 + pc * 8) * 2);
                bfv[dt * 2][0]     = t4[0];
                bfv[dt * 2][1]     = t4[2];
                bfv[dt * 2 + 1][0] = t4[1];
                bfv[dt * 2 + 1][1] = t4[3];
            }
            #pragma unroll
            for (int mt = 0; mt < 2; mt++) {
                uint32_t ap[4];
                ap[0] = packh2(s[mt][2 * ks][0],     s[mt][2 * ks][1]);
                ap[1] = packh2(s[mt][2 * ks][2],     s[mt][2 * ks][3]);
                ap[2] = packh2(s[mt][2 * ks + 1][0], s[mt][2 * ks + 1][1]);
                ap[3] = packh2(s[mt][2 * ks + 1][2], s[mt][2 * ks + 1][3]);
                #pragma unroll
                for (int nt = 0; nt < 8; nt++)
                    mma_f16(o[mt][nt], ap, bfv[nt]);
            }
        }

        buf = (buf + 1) % FA_STG;
    }

    // epilogue: normalize, fp16 out
    __half* ob = out + ((size_t)b * SEQ + q0) * DIMQ + h * DHEAD;
    #pragma unroll
    for (int mt = 0; mt < 2; mt++) {
        const float inv_lo = 1.f / li[mt][0];
        const float inv_hi = 1.f / li[mt][1];
        const int m = wr + mt * 16 + lq;
        #pragma unroll
        for (int nt = 0; nt < 8; nt++) {
            const int col = nt * 8 + 2 * lr;
            *(__half2*)(ob + (size_t)m * DIMQ + col) =
                __floats2half2_rn(o[mt][nt][0] * inv_lo, o[mt][nt][1] * inv_lo);
            *(__half2*)(ob + (size_t)(m + 8) * DIMQ + col) =
                __floats2half2_rn(o[mt][nt][2] * inv_hi, o[mt][nt][3] * inv_hi);
        }
    }
}

// ---------------------------------------------------------------------------
// Launch
// ---------------------------------------------------------------------------
extern "C" void kernel_launch(void* const* d_in, const int* in_sizes, int n_in,
                              void* d_out, int out_size)
{
    const float* x    = (const float*)d_in[0];   // [2,2048,1024]
    const float* Wqkv = (const float*)d_in[1];   // [1024,3072]
    const float* Wout = (const float*)d_in[2];   // [1024,1024]
    const float* bout = (const float*)d_in[3];   // [1024]
    float* out = (float*)d_out;                  // [2,2048,1024] f32

    __half *qkv, *att, *xh, *wqkvT, *woutT;
    cudaGetSymbolAddress((void**)&qkv, g_qkv);
    cudaGetSymbolAddress((void**)&att, g_att);
    cudaGetSymbolAddress((void**)&xh, g_xh);
    cudaGetSymbolAddress((void**)&wqkvT, g_wqkvT);
    cudaGetSymbolAddress((void**)&woutT, g_woutT);

    cudaFuncSetAttribute(gemm_f16,
                         cudaFuncAttributeMaxDynamicSharedMemorySize, GEMM_SMEM);
    cudaFuncSetAttribute(flash_attn_f16,
                         cudaFuncAttributeMaxDynamicSharedMemorySize, FA_SMEM);

    // Stage 0: convert x to fp16; convert+transpose weights to [n][k] fp16
    {
        int nx = NTOK * DIMQ;
        f32_to_f16<<<nx / 8 / 256, 256>>>(x, xh, nx);
        f32_to_f16_T<<<dim3(QKV_N / 32, DIMQ / 32), dim3(32, 8)>>>(
            Wqkv, wqkvT, DIMQ, QKV_N);
        f32_to_f16_T<<<dim3(DIMQ / 32, DIMQ / 32), dim3(32, 8)>>>(
            Wout, woutT, DIMQ, DIMQ);
    }

    // Stage 1: qkv = x @ W_qkv  (4096 x 3072 x 1024), fp16 out
    {
        dim3 grid(QKV_N / 128, NTOK / 128);
        gemm_f16<<<grid, 128, GEMM_SMEM>>>(xh, wqkvT, nullptr, qkv,
                                           NTOK, QKV_N, DIMQ, 1);
    }

    // Stage 2: flash attention (128 q-rows per CTA, 4 warps), fp16 out
    {
        dim3 grid(SEQ / 128, HEADS, BATCH);
        flash_attn_f16<<<grid, 128, FA_SMEM>>>(qkv, att);
    }

    // Stage 3: out = att @ W_out + b_out  (4096 x 1024 x 1024), f32 out
    {
        dim3 grid(DIMQ / 128, NTOK / 128);
        gemm_f16<<<grid, 128, GEMM_SMEM>>>(att, woutT, bout, out,
                                           NTOK, DIMQ, DIMQ, 0);
    }
}